// round 1
// baseline (speedup 1.0000x reference)
#include <cuda_runtime.h>
#include <cuda_bf16.h>
#include <math.h>

#define NN   50000
#define EE   800000
#define DIN  256
#define DH   128

// ---------------- scratch (static device globals; no allocation) ----------------
__device__ __align__(16) float g_C1[(size_t)NN * 384];   // x@[Wl0|Wr0|Wp]
__device__ __align__(16) float g_agg[(size_t)NN * DH];   // segment sums (reused)
__device__ __align__(16) float g_h1[(size_t)NN * DH];
__device__ __align__(16) float g_C2[(size_t)NN * 256];   // h1@[Wl1|Wr1]
__device__ __align__(16) float g_h2[(size_t)NN * DH];
__device__ int   g_deg[NN];
__device__ __align__(16) float g_Bp1[DIN * 384];
__device__ __align__(16) float g_Bp2[DH * 256];

// ---------------- helpers ----------------
__global__ void zero_f4(float4* p, int n4) {
    int i = blockIdx.x * blockDim.x + threadIdx.x;
    if (i < n4) p[i] = make_float4(0.f, 0.f, 0.f, 0.f);
}
__global__ void zero_i(int* p, int n) {
    int i = blockIdx.x * blockDim.x + threadIdx.x;
    if (i < n) p[i] = 0;
}

// pack B for GEMM1: [DIN, 384] = Wl0 | Wr0 | Wp  (all [DIN, DH] row-major)
__global__ void pack1_kernel(const float* __restrict__ Wl0, const float* __restrict__ Wr0,
                             const float* __restrict__ Wp) {
    int idx = blockIdx.x * blockDim.x + threadIdx.x;
    if (idx >= DIN * 384) return;
    int k = idx / 384, j = idx % 384;
    float v;
    if (j < 128)       v = Wl0[k * DH + j];
    else if (j < 256)  v = Wr0[k * DH + (j - 128)];
    else               v = Wp [k * DH + (j - 256)];
    g_Bp1[idx] = v;
}

// pack B for GEMM2: [DH, 256] = Wl1 | Wr1
__global__ void pack2_kernel(const float* __restrict__ Wl1, const float* __restrict__ Wr1) {
    int idx = blockIdx.x * blockDim.x + threadIdx.x;
    if (idx >= DH * 256) return;
    int k = idx / 256, j = idx % 256;
    g_Bp2[idx] = (j < 128) ? Wl1[k * DH + j] : Wr1[k * DH + (j - 128)];
}

// ---------------- SGEMM: C[M,Ncol] = A[M,K] @ B[K,Ncol], 128x128x8 tile ----------------
__global__ __launch_bounds__(256)
void sgemm128(const float* __restrict__ A, const float* __restrict__ B,
              float* __restrict__ C, int M, int K, int Ncol) {
    __shared__ float As[8][132];
    __shared__ float Bs[8][132];

    const int tid = threadIdx.x;
    const int tx = tid % 16;          // col group
    const int ty = tid / 16;          // row group
    const int rowBase = blockIdx.y * 128;
    const int colBase = blockIdx.x * 128;

    const int aRow = tid >> 1;            // 0..127
    const int aCol = (tid & 1) * 4;       // 0 or 4
    const int bRow = tid >> 5;            // 0..7
    const int bCol = (tid & 31) * 4;      // 0..124

    float acc[8][8];
#pragma unroll
    for (int i = 0; i < 8; i++)
#pragma unroll
        for (int j = 0; j < 8; j++) acc[i][j] = 0.f;

    for (int k0 = 0; k0 < K; k0 += 8) {
        float4 av = make_float4(0.f, 0.f, 0.f, 0.f);
        if (rowBase + aRow < M)
            av = *(const float4*)(A + (size_t)(rowBase + aRow) * K + k0 + aCol);
        As[aCol + 0][aRow] = av.x;
        As[aCol + 1][aRow] = av.y;
        As[aCol + 2][aRow] = av.z;
        As[aCol + 3][aRow] = av.w;

        float4 bv = *(const float4*)(B + (size_t)(k0 + bRow) * Ncol + colBase + bCol);
        *(float4*)&Bs[bRow][bCol] = bv;
        __syncthreads();

#pragma unroll
        for (int kk = 0; kk < 8; kk++) {
            float a[8], b[8];
            *(float4*)&a[0] = *(const float4*)&As[kk][ty * 8];
            *(float4*)&a[4] = *(const float4*)&As[kk][ty * 8 + 4];
            *(float4*)&b[0] = *(const float4*)&Bs[kk][tx * 8];
            *(float4*)&b[4] = *(const float4*)&Bs[kk][tx * 8 + 4];
#pragma unroll
            for (int i = 0; i < 8; i++)
#pragma unroll
                for (int j = 0; j < 8; j++)
                    acc[i][j] = fmaf(a[i], b[j], acc[i][j]);
        }
        __syncthreads();
    }

#pragma unroll
    for (int i = 0; i < 8; i++) {
        int r = rowBase + ty * 8 + i;
        if (r < M) {
            float* crow = C + (size_t)r * Ncol + colBase + tx * 8;
            *(float4*)(crow + 0) = make_float4(acc[i][0], acc[i][1], acc[i][2], acc[i][3]);
            *(float4*)(crow + 4) = make_float4(acc[i][4], acc[i][5], acc[i][6], acc[i][7]);
        }
    }
}

// ---------------- edge aggregation: 1 warp per edge ----------------
// agg[dst] += Y[src, 0:128];  Y has row stride ldy.  Optionally counts degree.
__global__ void edge_agg_kernel(const float* __restrict__ Y, int ldy,
                                const int* __restrict__ src, const int* __restrict__ dst,
                                float* __restrict__ agg, int* __restrict__ deg, int E) {
    int gid = blockIdx.x * blockDim.x + threadIdx.x;
    int w = gid >> 5;
    int lane = gid & 31;
    if (w >= E) return;
    int s = src[w];
    int d = dst[w];
    float4 v = *((const float4*)(Y + (size_t)s * ldy) + lane);
    float* a = agg + (size_t)d * DH + lane * 4;
    asm volatile("red.global.add.v4.f32 [%0], {%1,%2,%3,%4};"
                 :: "l"(a), "f"(v.x), "f"(v.y), "f"(v.z), "f"(v.w) : "memory");
    if (deg != nullptr && lane == 0) atomicAdd(deg + d, 1);
}

// ---------------- node epilogue conv0 ----------------
// h1 = relu(agg/deg + bl0 + r0) + (proj + bp)      r0 = C1[:,128:256], proj = C1[:,256:384]
__global__ void node0_kernel(const float* __restrict__ bl0, const float* __restrict__ bp, int N) {
    int idx = blockIdx.x * blockDim.x + threadIdx.x;
    if (idx >= N * 32) return;
    int i = idx >> 5, c = idx & 31;
    float dinv = 1.0f / fmaxf((float)g_deg[i], 1.0f);
    float4 a  = *(const float4*)(g_agg + (size_t)i * DH + c * 4);
    float4 r  = *(const float4*)(g_C1 + (size_t)i * 384 + 128 + c * 4);
    float4 p  = *(const float4*)(g_C1 + (size_t)i * 384 + 256 + c * 4);
    float4 bl = *(const float4*)(bl0 + c * 4);
    float4 bv = *(const float4*)(bp + c * 4);
    float4 o;
    o.x = fmaxf(fmaf(a.x, dinv, bl.x + r.x), 0.f) + p.x + bv.x;
    o.y = fmaxf(fmaf(a.y, dinv, bl.y + r.y), 0.f) + p.y + bv.y;
    o.z = fmaxf(fmaf(a.z, dinv, bl.z + r.z), 0.f) + p.z + bv.z;
    o.w = fmaxf(fmaf(a.w, dinv, bl.w + r.w), 0.f) + p.w + bv.w;
    *(float4*)(g_h1 + (size_t)i * DH + c * 4) = o;
}

// ---------------- node epilogue conv1 ----------------
// h2 = relu(agg/deg + bl1 + r1) + h1               r1 = C2[:,128:256]
__global__ void node1_kernel(const float* __restrict__ bl1, int N) {
    int idx = blockIdx.x * blockDim.x + threadIdx.x;
    if (idx >= N * 32) return;
    int i = idx >> 5, c = idx & 31;
    float dinv = 1.0f / fmaxf((float)g_deg[i], 1.0f);
    float4 a  = *(const float4*)(g_agg + (size_t)i * DH + c * 4);
    float4 r  = *(const float4*)(g_C2 + (size_t)i * 256 + 128 + c * 4);
    float4 hp = *(const float4*)(g_h1 + (size_t)i * DH + c * 4);
    float4 bl = *(const float4*)(bl1 + c * 4);
    float4 o;
    o.x = fmaxf(fmaf(a.x, dinv, bl.x + r.x), 0.f) + hp.x;
    o.y = fmaxf(fmaf(a.y, dinv, bl.y + r.y), 0.f) + hp.y;
    o.z = fmaxf(fmaf(a.z, dinv, bl.z + r.z), 0.f) + hp.z;
    o.w = fmaxf(fmaf(a.w, dinv, bl.w + r.w), 0.f) + hp.w;
    *(float4*)(g_h2 + (size_t)i * DH + c * 4) = o;
}

// ---------------- fused MLP head + blend ----------------
// out = alpha*rer + (1-alpha)*(relu(h2@W1+b1)@W2 + b2),  alpha = sigmoid(alpha_logit)
__global__ __launch_bounds__(256)
void head_kernel(const float* __restrict__ W1, const float* __restrict__ b1,
                 const float* __restrict__ W2, const float* __restrict__ b2,
                 const float* __restrict__ rer, const float* __restrict__ alogit,
                 float* __restrict__ out, int N) {
    __shared__ float W1s[128 * 64];
    __shared__ float b1s[64];
    __shared__ float W2s[64];

    for (int k = threadIdx.x; k < 128 * 64; k += blockDim.x) W1s[k] = W1[k];
    if (threadIdx.x < 64) { b1s[threadIdx.x] = b1[threadIdx.x]; W2s[threadIdx.x] = W2[threadIdx.x]; }
    __syncthreads();

    int i = blockIdx.x * blockDim.x + threadIdx.x;
    if (i >= N) return;

    float acc[64];
#pragma unroll
    for (int j = 0; j < 64; j++) acc[j] = b1s[j];

    const float4* h4 = (const float4*)(g_h2 + (size_t)i * DH);
#pragma unroll 4
    for (int k4 = 0; k4 < 32; k4++) {
        float4 xv = h4[k4];
        float xs[4] = {xv.x, xv.y, xv.z, xv.w};
#pragma unroll
        for (int kk = 0; kk < 4; kk++) {
            float xk = xs[kk];
            int k = k4 * 4 + kk;
            const float4* wrow = (const float4*)&W1s[k * 64];
#pragma unroll
            for (int j4 = 0; j4 < 16; j4++) {
                float4 w = wrow[j4];
                acc[j4 * 4 + 0] = fmaf(xk, w.x, acc[j4 * 4 + 0]);
                acc[j4 * 4 + 1] = fmaf(xk, w.y, acc[j4 * 4 + 1]);
                acc[j4 * 4 + 2] = fmaf(xk, w.z, acc[j4 * 4 + 2]);
                acc[j4 * 4 + 3] = fmaf(xk, w.w, acc[j4 * 4 + 3]);
            }
        }
    }

    float s = b2[0];
#pragma unroll
    for (int j = 0; j < 64; j++) s = fmaf(fmaxf(acc[j], 0.f), W2s[j], s);

    float alpha = 1.0f / (1.0f + __expf(-alogit[0]));
    out[i] = alpha * rer[i] + (1.0f - alpha) * s;
}

// ---------------- launch ----------------
extern "C" void kernel_launch(void* const* d_in, const int* in_sizes, int n_in,
                              void* d_out, int out_size) {
    const float* x     = (const float*)d_in[0];
    const int*   eidx  = (const int*)d_in[1];
    const float* rer   = (const float*)d_in[2];
    const float* Wp    = (const float*)d_in[3];
    const float* bp    = (const float*)d_in[4];
    const float* Wl0   = (const float*)d_in[5];
    const float* bl0   = (const float*)d_in[6];
    const float* Wr0   = (const float*)d_in[7];
    const float* Wl1   = (const float*)d_in[8];
    const float* bl1   = (const float*)d_in[9];
    const float* Wr1   = (const float*)d_in[10];
    const float* W1    = (const float*)d_in[11];
    const float* b1    = (const float*)d_in[12];
    const float* W2    = (const float*)d_in[13];
    const float* b2    = (const float*)d_in[14];
    const float* alog  = (const float*)d_in[15];
    float* out = (float*)d_out;

    const int N = in_sizes[0] / DIN;       // 50000
    const int E = in_sizes[1] / 2;         // 800000
    const int* src = eidx;
    const int* dst = eidx + E;

    float *C1, *agg, *h1, *C2, *Bp1, *Bp2;
    int* deg;
    cudaGetSymbolAddress((void**)&C1,  g_C1);
    cudaGetSymbolAddress((void**)&agg, g_agg);
    cudaGetSymbolAddress((void**)&h1,  g_h1);
    cudaGetSymbolAddress((void**)&C2,  g_C2);
    cudaGetSymbolAddress((void**)&Bp1, g_Bp1);
    cudaGetSymbolAddress((void**)&Bp2, g_Bp2);
    cudaGetSymbolAddress((void**)&deg, g_deg);

    // pack fused weight matrices
    pack1_kernel<<<(DIN * 384 + 255) / 256, 256>>>(Wl0, Wr0, Wp);
    pack2_kernel<<<(DH * 256 + 255) / 256, 256>>>(Wl1, Wr1);

    // zero aggregation buffers
    int n4 = N * DH / 4;
    zero_f4<<<(n4 + 255) / 256, 256>>>((float4*)agg, n4);
    zero_i<<<(N + 255) / 256, 256>>>(deg, N);

    // GEMM1: C1 = x @ [Wl0 | Wr0 | Wp]   -> [N, 384]
    {
        dim3 grid(384 / 128, (N + 127) / 128);
        sgemm128<<<grid, 256>>>(x, Bp1, C1, N, DIN, 384);
    }

    // conv0 edge aggregation over projected messages (y0 = C1[:,0:128]), + degree
    {
        int warps = E;
        int blocks = (warps * 32 + 255) / 256;
        edge_agg_kernel<<<blocks, 256>>>(C1, 384, src, dst, agg, deg, E);
    }

    // h1 = relu(agg/deg + bl0 + x@Wr0) + (x@Wp + bp)
    node0_kernel<<<(N * 32 + 255) / 256, 256>>>(bl0, bp, N);

    // GEMM2: C2 = h1 @ [Wl1 | Wr1]       -> [N, 256]
    {
        dim3 grid(256 / 128, (N + 127) / 128);
        sgemm128<<<grid, 256>>>(h1, Bp2, C2, N, DH, 256);
    }

    // conv1 edge aggregation (re-zero agg, keep deg)
    zero_f4<<<(n4 + 255) / 256, 256>>>((float4*)agg, n4);
    {
        int warps = E;
        int blocks = (warps * 32 + 255) / 256;
        edge_agg_kernel<<<blocks, 256>>>(C2, 256, src, dst, agg, nullptr, E);
    }

    // h2 = relu(agg/deg + bl1 + h1@Wr1) + h1
    node1_kernel<<<(N * 32 + 255) / 256, 256>>>(bl1, N);

    // MLP head + blend
    head_kernel<<<(N + 255) / 256, 256>>>(W1, b1, W2, b2, rer, alog, out, N);
}

// round 2
// speedup vs baseline: 1.3821x; 1.3821x over previous
#include <cuda_runtime.h>
#include <cuda_bf16.h>
#include <math.h>
#include <stdint.h>

#define NN   50000
#define EE   800000
#define DIN  256
#define DH   128

// ---------------- scratch (static device globals; no allocation) ----------------
__device__ __align__(16) float g_C1[(size_t)NN * 384];   // x@[Wl0|Wr0|Wp]
__device__ __align__(16) float g_agg[(size_t)NN * DH];   // segment sums (reused)
__device__ __align__(16) float g_h1[(size_t)NN * DH];
__device__ __align__(16) float g_C2[(size_t)NN * 256];   // h1@[Wl1|Wr1]
__device__ __align__(16) float g_h2[(size_t)NN * DH];
__device__ int   g_deg[NN];
__device__ __align__(16) float g_Bp1[DIN * 384];
__device__ __align__(16) float g_Bp2[DH * 256];

// ---------------- helpers ----------------
__global__ void zero_all(float4* agg4, int n4, int* deg, int n) {
    int i = blockIdx.x * blockDim.x + threadIdx.x;
    if (i < n4) agg4[i] = make_float4(0.f, 0.f, 0.f, 0.f);
    if (i < n) deg[i] = 0;
}
__global__ void zero_f4(float4* p, int n4) {
    int i = blockIdx.x * blockDim.x + threadIdx.x;
    if (i < n4) p[i] = make_float4(0.f, 0.f, 0.f, 0.f);
}

// pack both fused B matrices in one launch
__global__ void pack_kernel(const float* __restrict__ Wl0, const float* __restrict__ Wr0,
                            const float* __restrict__ Wp,
                            const float* __restrict__ Wl1, const float* __restrict__ Wr1) {
    int idx = blockIdx.x * blockDim.x + threadIdx.x;
    if (idx < DIN * 384) {
        int k = idx / 384, j = idx % 384;
        float v;
        if (j < 128)       v = Wl0[k * DH + j];
        else if (j < 256)  v = Wr0[k * DH + (j - 128)];
        else               v = Wp [k * DH + (j - 256)];
        g_Bp1[idx] = v;
    }
    if (idx < DH * 256) {
        int k = idx / 256, j = idx % 256;
        g_Bp2[idx] = (j < 128) ? Wl1[k * DH + j] : Wr1[k * DH + (j - 128)];
    }
}

// ---------------- TF32 tensor-core GEMM ----------------
// C[M,Ncol] = A[M,K] @ B[K,Ncol], fp32 in/out, tf32 mma (m16n8k8), fp32 accum.
// Block tile 128x128, k-chunk 32. 8 warps = 2(M) x 4(N), warp tile 64x32.

__device__ __forceinline__ uint32_t f2tf32(float f) {
    uint32_t u;
    asm("cvt.rna.tf32.f32 %0, %1;" : "=r"(u) : "f"(f));
    return u;
}

__device__ __forceinline__ void mma_tf32(float c[4], uint32_t a0, uint32_t a1,
                                         uint32_t a2, uint32_t a3,
                                         uint32_t b0, uint32_t b1) {
    asm volatile(
        "mma.sync.aligned.m16n8k8.row.col.f32.tf32.tf32.f32 "
        "{%0,%1,%2,%3}, {%4,%5,%6,%7}, {%8,%9}, {%0,%1,%2,%3};"
        : "+f"(c[0]), "+f"(c[1]), "+f"(c[2]), "+f"(c[3])
        : "r"(a0), "r"(a1), "r"(a2), "r"(a3), "r"(b0), "r"(b1));
}

__global__ __launch_bounds__(256)
void gemm_tf32(const float* __restrict__ A, const float* __restrict__ B,
               float* __restrict__ C, int M, int K, int Ncol) {
    __shared__ uint32_t As[128][36];   // [m][k], pad 36 -> conflict-free frag loads
    __shared__ uint32_t Bs[32][132];   // [k][n], pad 132 -> conflict-free frag loads

    const int t = threadIdx.x;
    const int lane = t & 31;
    const int warp = t >> 5;
    const int wm = (warp & 1) * 64;    // warp M offset in tile
    const int wn = (warp >> 1) * 32;   // warp N offset in tile
    const int g = lane >> 2;           // group id 0..7
    const int t4 = lane & 3;           // thread in group 0..3

    const int rowBase = blockIdx.y * 128;
    const int colBase = blockIdx.x * 128;

    // A staging: thread -> row (t>>1), 16 consecutive cols at (t&1)*16
    const int ar = t >> 1;
    const int ac = (t & 1) * 16;
    // B staging: thread -> row (t>>3), 16 consecutive cols at (t&7)*16
    const int br = t >> 3;
    const int bc = (t & 7) * 16;

    float acc[4][4][4];
#pragma unroll
    for (int mt = 0; mt < 4; mt++)
#pragma unroll
        for (int nt = 0; nt < 4; nt++)
#pragma unroll
            for (int i = 0; i < 4; i++) acc[mt][nt][i] = 0.f;

    const int grow = rowBase + ar;

    for (int k0 = 0; k0 < K; k0 += 32) {
        // stage A (convert to tf32)
        {
            float v[16];
            if (grow < M) {
                const float4* ap = (const float4*)(A + (size_t)grow * K + k0 + ac);
#pragma unroll
                for (int q = 0; q < 4; q++) {
                    float4 x = ap[q];
                    v[q * 4 + 0] = x.x; v[q * 4 + 1] = x.y;
                    v[q * 4 + 2] = x.z; v[q * 4 + 3] = x.w;
                }
            } else {
#pragma unroll
                for (int j = 0; j < 16; j++) v[j] = 0.f;
            }
            uint32_t* dstp = &As[ar][ac];
#pragma unroll
            for (int q = 0; q < 4; q++) {
                uint4 u;
                u.x = f2tf32(v[q * 4 + 0]); u.y = f2tf32(v[q * 4 + 1]);
                u.z = f2tf32(v[q * 4 + 2]); u.w = f2tf32(v[q * 4 + 3]);
                *(uint4*)(dstp + q * 4) = u;
            }
        }
        // stage B (convert to tf32)
        {
            const float4* bp = (const float4*)(B + (size_t)(k0 + br) * Ncol + colBase + bc);
            uint32_t* dstp = &Bs[br][bc];
#pragma unroll
            for (int q = 0; q < 4; q++) {
                float4 x = bp[q];
                uint4 u;
                u.x = f2tf32(x.x); u.y = f2tf32(x.y);
                u.z = f2tf32(x.z); u.w = f2tf32(x.w);
                *(uint4*)(dstp + q * 4) = u;
            }
        }
        __syncthreads();

#pragma unroll
        for (int kk = 0; kk < 4; kk++) {
            const int kb = kk * 8;
            uint32_t af[4][4];
#pragma unroll
            for (int mt = 0; mt < 4; mt++) {
                int r = wm + mt * 16 + g;
                af[mt][0] = As[r][kb + t4];
                af[mt][1] = As[r + 8][kb + t4];
                af[mt][2] = As[r][kb + t4 + 4];
                af[mt][3] = As[r + 8][kb + t4 + 4];
            }
#pragma unroll
            for (int nt = 0; nt < 4; nt++) {
                int cn = wn + nt * 8 + g;
                uint32_t b0 = Bs[kb + t4][cn];
                uint32_t b1 = Bs[kb + t4 + 4][cn];
#pragma unroll
                for (int mt = 0; mt < 4; mt++)
                    mma_tf32(acc[mt][nt], af[mt][0], af[mt][1], af[mt][2], af[mt][3], b0, b1);
            }
        }
        __syncthreads();
    }

    // epilogue: c0,c1 at (g, 2*t4), c2,c3 at (g+8, 2*t4)
#pragma unroll
    for (int mt = 0; mt < 4; mt++) {
        int r0 = rowBase + wm + mt * 16 + g;
#pragma unroll
        for (int nt = 0; nt < 4; nt++) {
            int col = colBase + wn + nt * 8 + 2 * t4;
            if (r0 < M)
                *(float2*)(C + (size_t)r0 * Ncol + col) = make_float2(acc[mt][nt][0], acc[mt][nt][1]);
            if (r0 + 8 < M)
                *(float2*)(C + (size_t)(r0 + 8) * Ncol + col) = make_float2(acc[mt][nt][2], acc[mt][nt][3]);
        }
    }
}

// ---------------- edge aggregation: 1 warp per edge ----------------
__global__ void edge_agg_kernel(const float* __restrict__ Y, int ldy,
                                const int* __restrict__ src, const int* __restrict__ dst,
                                float* __restrict__ agg, int* __restrict__ deg, int E) {
    int gid = blockIdx.x * blockDim.x + threadIdx.x;
    int w = gid >> 5;
    int lane = gid & 31;
    if (w >= E) return;
    int s = src[w];
    int d = dst[w];
    float4 v = *((const float4*)(Y + (size_t)s * ldy) + lane);
    float* a = agg + (size_t)d * DH + lane * 4;
    asm volatile("red.global.add.v4.f32 [%0], {%1,%2,%3,%4};"
                 :: "l"(a), "f"(v.x), "f"(v.y), "f"(v.z), "f"(v.w) : "memory");
    if (deg != nullptr && lane == 0) atomicAdd(deg + d, 1);
}

// ---------------- node epilogue conv0 ----------------
__global__ void node0_kernel(const float* __restrict__ bl0, const float* __restrict__ bp, int N) {
    int idx = blockIdx.x * blockDim.x + threadIdx.x;
    if (idx >= N * 32) return;
    int i = idx >> 5, c = idx & 31;
    float dinv = 1.0f / fmaxf((float)g_deg[i], 1.0f);
    float4 a  = *(const float4*)(g_agg + (size_t)i * DH + c * 4);
    float4 r  = *(const float4*)(g_C1 + (size_t)i * 384 + 128 + c * 4);
    float4 p  = *(const float4*)(g_C1 + (size_t)i * 384 + 256 + c * 4);
    float4 bl = *(const float4*)(bl0 + c * 4);
    float4 bv = *(const float4*)(bp + c * 4);
    float4 o;
    o.x = fmaxf(fmaf(a.x, dinv, bl.x + r.x), 0.f) + p.x + bv.x;
    o.y = fmaxf(fmaf(a.y, dinv, bl.y + r.y), 0.f) + p.y + bv.y;
    o.z = fmaxf(fmaf(a.z, dinv, bl.z + r.z), 0.f) + p.z + bv.z;
    o.w = fmaxf(fmaf(a.w, dinv, bl.w + r.w), 0.f) + p.w + bv.w;
    *(float4*)(g_h1 + (size_t)i * DH + c * 4) = o;
}

// ---------------- node epilogue conv1 ----------------
__global__ void node1_kernel(const float* __restrict__ bl1, int N) {
    int idx = blockIdx.x * blockDim.x + threadIdx.x;
    if (idx >= N * 32) return;
    int i = idx >> 5, c = idx & 31;
    float dinv = 1.0f / fmaxf((float)g_deg[i], 1.0f);
    float4 a  = *(const float4*)(g_agg + (size_t)i * DH + c * 4);
    float4 r  = *(const float4*)(g_C2 + (size_t)i * 256 + 128 + c * 4);
    float4 hp = *(const float4*)(g_h1 + (size_t)i * DH + c * 4);
    float4 bl = *(const float4*)(bl1 + c * 4);
    float4 o;
    o.x = fmaxf(fmaf(a.x, dinv, bl.x + r.x), 0.f) + hp.x;
    o.y = fmaxf(fmaf(a.y, dinv, bl.y + r.y), 0.f) + hp.y;
    o.z = fmaxf(fmaf(a.z, dinv, bl.z + r.z), 0.f) + hp.z;
    o.w = fmaxf(fmaf(a.w, dinv, bl.w + r.w), 0.f) + hp.w;
    *(float4*)(g_h2 + (size_t)i * DH + c * 4) = o;
}

// ---------------- fused MLP head + blend ----------------
__global__ __launch_bounds__(256)
void head_kernel(const float* __restrict__ W1, const float* __restrict__ b1,
                 const float* __restrict__ W2, const float* __restrict__ b2,
                 const float* __restrict__ rer, const float* __restrict__ alogit,
                 float* __restrict__ out, int N) {
    __shared__ float W1s[128 * 64];
    __shared__ float b1s[64];
    __shared__ float W2s[64];

    for (int k = threadIdx.x; k < 128 * 64; k += blockDim.x) W1s[k] = W1[k];
    if (threadIdx.x < 64) { b1s[threadIdx.x] = b1[threadIdx.x]; W2s[threadIdx.x] = W2[threadIdx.x]; }
    __syncthreads();

    int i = blockIdx.x * blockDim.x + threadIdx.x;
    if (i >= N) return;

    float acc[64];
#pragma unroll
    for (int j = 0; j < 64; j++) acc[j] = b1s[j];

    const float4* h4 = (const float4*)(g_h2 + (size_t)i * DH);
#pragma unroll 4
    for (int k4 = 0; k4 < 32; k4++) {
        float4 xv = h4[k4];
        float xs[4] = {xv.x, xv.y, xv.z, xv.w};
#pragma unroll
        for (int kk = 0; kk < 4; kk++) {
            float xk = xs[kk];
            int k = k4 * 4 + kk;
            const float4* wrow = (const float4*)&W1s[k * 64];
#pragma unroll
            for (int j4 = 0; j4 < 16; j4++) {
                float4 w = wrow[j4];
                acc[j4 * 4 + 0] = fmaf(xk, w.x, acc[j4 * 4 + 0]);
                acc[j4 * 4 + 1] = fmaf(xk, w.y, acc[j4 * 4 + 1]);
                acc[j4 * 4 + 2] = fmaf(xk, w.z, acc[j4 * 4 + 2]);
                acc[j4 * 4 + 3] = fmaf(xk, w.w, acc[j4 * 4 + 3]);
            }
        }
    }

    float s = b2[0];
#pragma unroll
    for (int j = 0; j < 64; j++) s = fmaf(fmaxf(acc[j], 0.f), W2s[j], s);

    float alpha = 1.0f / (1.0f + __expf(-alogit[0]));
    out[i] = alpha * rer[i] + (1.0f - alpha) * s;
}

// ---------------- launch ----------------
extern "C" void kernel_launch(void* const* d_in, const int* in_sizes, int n_in,
                              void* d_out, int out_size) {
    const float* x     = (const float*)d_in[0];
    const int*   eidx  = (const int*)d_in[1];
    const float* rer   = (const float*)d_in[2];
    const float* Wp    = (const float*)d_in[3];
    const float* bp    = (const float*)d_in[4];
    const float* Wl0   = (const float*)d_in[5];
    const float* bl0   = (const float*)d_in[6];
    const float* Wr0   = (const float*)d_in[7];
    const float* Wl1   = (const float*)d_in[8];
    const float* bl1   = (const float*)d_in[9];
    const float* Wr1   = (const float*)d_in[10];
    const float* W1    = (const float*)d_in[11];
    const float* b1    = (const float*)d_in[12];
    const float* W2    = (const float*)d_in[13];
    const float* b2    = (const float*)d_in[14];
    const float* alog  = (const float*)d_in[15];
    float* out = (float*)d_out;

    const int N = in_sizes[0] / DIN;       // 50000
    const int E = in_sizes[1] / 2;         // 800000
    const int* src = eidx;
    const int* dst = eidx + E;

    float *C1, *agg, *h1, *C2, *Bp1, *Bp2;
    int* deg;
    cudaGetSymbolAddress((void**)&C1,  g_C1);
    cudaGetSymbolAddress((void**)&agg, g_agg);
    cudaGetSymbolAddress((void**)&h1,  g_h1);
    cudaGetSymbolAddress((void**)&C2,  g_C2);
    cudaGetSymbolAddress((void**)&Bp1, g_Bp1);
    cudaGetSymbolAddress((void**)&Bp2, g_Bp2);
    cudaGetSymbolAddress((void**)&deg, g_deg);

    // pack fused weight matrices (one launch)
    pack_kernel<<<(DIN * 384 + 255) / 256, 256>>>(Wl0, Wr0, Wp, Wl1, Wr1);

    // zero aggregation buffer + degree
    int n4 = N * DH / 4;
    zero_all<<<(n4 + 255) / 256, 256>>>((float4*)agg, n4, deg, N);

    // GEMM1: C1 = x @ [Wl0 | Wr0 | Wp]   -> [N, 384]  (tf32 tensor cores)
    {
        dim3 grid(384 / 128, (N + 127) / 128);
        gemm_tf32<<<grid, 256>>>(x, Bp1, C1, N, DIN, 384);
    }

    // conv0 edge aggregation over projected messages (y0 = C1[:,0:128]), + degree
    {
        int blocks = (E * 32 + 255) / 256;
        edge_agg_kernel<<<blocks, 256>>>(C1, 384, src, dst, agg, deg, E);
    }

    // h1 = relu(agg/deg + bl0 + x@Wr0) + (x@Wp + bp)
    node0_kernel<<<(N * 32 + 255) / 256, 256>>>(bl0, bp, N);

    // GEMM2: C2 = h1 @ [Wl1 | Wr1]       -> [N, 256]
    {
        dim3 grid(256 / 128, (N + 127) / 128);
        gemm_tf32<<<grid, 256>>>(h1, Bp2, C2, N, DH, 256);
    }

    // conv1 edge aggregation (re-zero agg, keep deg)
    zero_f4<<<(n4 + 255) / 256, 256>>>((float4*)agg, n4);
    {
        int blocks = (E * 32 + 255) / 256;
        edge_agg_kernel<<<blocks, 256>>>(C2, 256, src, dst, agg, nullptr, E);
    }

    // h2 = relu(agg/deg + bl1 + h1@Wr1) + h1
    node1_kernel<<<(N * 32 + 255) / 256, 256>>>(bl1, N);

    // MLP head + blend
    head_kernel<<<(N + 255) / 256, 256>>>(W1, b1, W2, b2, rer, alog, out, N);
}

// round 3
// speedup vs baseline: 1.7658x; 1.2776x over previous
#include <cuda_runtime.h>
#include <cuda_bf16.h>
#include <math.h>
#include <stdint.h>

#define NN   50000
#define EE   800000
#define DIN  256
#define DH   128

// ---------------- scratch (static device globals; no allocation) ----------------
__device__ __align__(16) float g_C1[(size_t)NN * 384];   // x@[Wl0|Wr0|Wp] (cols 0:128 unused fp32)
__device__ __align__(16) float g_h1[(size_t)NN * DH];
__device__ __align__(16) float g_C2[(size_t)NN * 256];   // h1@[Wl1|Wr1]
__device__ __align__(16) float g_h2[(size_t)NN * DH];
__device__ __align__(16) __nv_bfloat16 g_msg1[(size_t)NN * DH];  // bf16 messages layer 0
__device__ __align__(16) __nv_bfloat16 g_msg2[(size_t)NN * DH];  // bf16 messages layer 1
__device__ __align__(16) __nv_bfloat16 g_agg1[(size_t)NN * DH];  // bf16 segment sums
__device__ __align__(16) __nv_bfloat16 g_agg2[(size_t)NN * DH];
__device__ int   g_deg[NN];
__device__ __align__(16) float g_Bp1[DIN * 384];
__device__ __align__(16) float g_Bp2[DH * 256];

// ---------------- zero everything in one launch ----------------
__global__ void zero_all(int n16, int n) {
    int i = blockIdx.x * blockDim.x + threadIdx.x;
    if (i < n16) {
        ((uint4*)g_agg1)[i] = make_uint4(0, 0, 0, 0);
        ((uint4*)g_agg2)[i] = make_uint4(0, 0, 0, 0);
    }
    if (i < n) g_deg[i] = 0;
}

// pack both fused B matrices in one launch
__global__ void pack_kernel(const float* __restrict__ Wl0, const float* __restrict__ Wr0,
                            const float* __restrict__ Wp,
                            const float* __restrict__ Wl1, const float* __restrict__ Wr1) {
    int idx = blockIdx.x * blockDim.x + threadIdx.x;
    if (idx < DIN * 384) {
        int k = idx / 384, j = idx % 384;
        float v;
        if (j < 128)       v = Wl0[k * DH + j];
        else if (j < 256)  v = Wr0[k * DH + (j - 128)];
        else               v = Wp [k * DH + (j - 256)];
        g_Bp1[idx] = v;
    }
    if (idx < DH * 256) {
        int k = idx / 256, j = idx % 256;
        g_Bp2[idx] = (j < 128) ? Wl1[k * DH + j] : Wr1[k * DH + (j - 128)];
    }
}

// ---------------- TF32 tensor-core GEMM, software-pipelined ----------------
// C[M,Ncol] = A[M,K] @ B[K,Ncol]. Block tile 128x128, k-chunk 32,
// 8 warps = 2(M) x 4(N), warp tile 64x32. If msg != nullptr, the column
// block at colBase==0 is written ONLY as bf16 into msg (row stride DH).

__device__ __forceinline__ uint32_t f2tf32(float f) {
    uint32_t u;
    asm("cvt.rna.tf32.f32 %0, %1;" : "=r"(u) : "f"(f));
    return u;
}

__device__ __forceinline__ void mma_tf32(float c[4], uint32_t a0, uint32_t a1,
                                         uint32_t a2, uint32_t a3,
                                         uint32_t b0, uint32_t b1) {
    asm volatile(
        "mma.sync.aligned.m16n8k8.row.col.f32.tf32.tf32.f32 "
        "{%0,%1,%2,%3}, {%4,%5,%6,%7}, {%8,%9}, {%0,%1,%2,%3};"
        : "+f"(c[0]), "+f"(c[1]), "+f"(c[2]), "+f"(c[3])
        : "r"(a0), "r"(a1), "r"(a2), "r"(a3), "r"(b0), "r"(b1));
}

__global__ __launch_bounds__(256)
void gemm_tf32(const float* __restrict__ A, const float* __restrict__ B,
               float* __restrict__ C, __nv_bfloat16* __restrict__ msg,
               int M, int K, int Ncol) {
    __shared__ uint32_t As[128][36];   // [m][k] pad 36 -> conflict-free frag loads
    __shared__ uint32_t Bs[32][132];   // [k][n] pad 132 -> conflict-free frag loads

    const int t = threadIdx.x;
    const int lane = t & 31;
    const int warp = t >> 5;
    const int wm = (warp & 1) * 64;
    const int wn = (warp >> 1) * 32;
    const int g = lane >> 2;
    const int t4 = lane & 3;

    const int rowBase = blockIdx.y * 128;
    const int colBase = blockIdx.x * 128;

    const int ar = t >> 1;
    const int ac = (t & 1) * 16;
    const int br = t >> 3;
    const int bc = (t & 7) * 16;

    float acc[4][4][4];
#pragma unroll
    for (int mt = 0; mt < 4; mt++)
#pragma unroll
        for (int nt = 0; nt < 4; nt++)
#pragma unroll
            for (int i = 0; i < 4; i++) acc[mt][nt][i] = 0.f;

    const int grow = rowBase + ar;
    const bool arow_ok = (grow < M);
    const float* aBase = A + (size_t)grow * K + ac;
    const float* bBase = B + (size_t)br * Ncol + colBase + bc;

    float ra[16], rb[16];

    // ---- preload chunk 0 ----
    {
        if (arow_ok) {
            const float4* ap = (const float4*)aBase;
#pragma unroll
            for (int q = 0; q < 4; q++) {
                float4 x = ap[q];
                ra[q*4+0] = x.x; ra[q*4+1] = x.y; ra[q*4+2] = x.z; ra[q*4+3] = x.w;
            }
        } else {
#pragma unroll
            for (int j = 0; j < 16; j++) ra[j] = 0.f;
        }
        const float4* bp = (const float4*)bBase;
#pragma unroll
        for (int q = 0; q < 4; q++) {
            float4 x = bp[q];
            rb[q*4+0] = x.x; rb[q*4+1] = x.y; rb[q*4+2] = x.z; rb[q*4+3] = x.w;
        }
    }

    const int nChunks = K >> 5;
    for (int ci = 0; ci < nChunks; ci++) {
        // ---- store current chunk to smem (convert to tf32) ----
        {
            uint32_t* dstp = &As[ar][ac];
#pragma unroll
            for (int q = 0; q < 4; q++) {
                uint4 u;
                u.x = f2tf32(ra[q*4+0]); u.y = f2tf32(ra[q*4+1]);
                u.z = f2tf32(ra[q*4+2]); u.w = f2tf32(ra[q*4+3]);
                *(uint4*)(dstp + q * 4) = u;
            }
            uint32_t* dstq = &Bs[br][bc];
#pragma unroll
            for (int q = 0; q < 4; q++) {
                uint4 u;
                u.x = f2tf32(rb[q*4+0]); u.y = f2tf32(rb[q*4+1]);
                u.z = f2tf32(rb[q*4+2]); u.w = f2tf32(rb[q*4+3]);
                *(uint4*)(dstq + q * 4) = u;
            }
        }
        __syncthreads();

        // ---- preload next chunk (overlaps with MMA below) ----
        if (ci + 1 < nChunks) {
            int k0 = (ci + 1) << 5;
            if (arow_ok) {
                const float4* ap = (const float4*)(aBase + k0);
#pragma unroll
                for (int q = 0; q < 4; q++) {
                    float4 x = ap[q];
                    ra[q*4+0] = x.x; ra[q*4+1] = x.y; ra[q*4+2] = x.z; ra[q*4+3] = x.w;
                }
            }
            const float4* bp = (const float4*)(bBase + (size_t)k0 * Ncol);
#pragma unroll
            for (int q = 0; q < 4; q++) {
                float4 x = bp[q];
                rb[q*4+0] = x.x; rb[q*4+1] = x.y; rb[q*4+2] = x.z; rb[q*4+3] = x.w;
            }
        }

        // ---- compute on smem ----
#pragma unroll
        for (int kk = 0; kk < 4; kk++) {
            const int kb = kk * 8;
            uint32_t af[4][4];
#pragma unroll
            for (int mt = 0; mt < 4; mt++) {
                int r = wm + mt * 16 + g;
                af[mt][0] = As[r][kb + t4];
                af[mt][1] = As[r + 8][kb + t4];
                af[mt][2] = As[r][kb + t4 + 4];
                af[mt][3] = As[r + 8][kb + t4 + 4];
            }
#pragma unroll
            for (int nt = 0; nt < 4; nt++) {
                int cn = wn + nt * 8 + g;
                uint32_t b0 = Bs[kb + t4][cn];
                uint32_t b1 = Bs[kb + t4 + 4][cn];
#pragma unroll
                for (int mt = 0; mt < 4; mt++)
                    mma_tf32(acc[mt][nt], af[mt][0], af[mt][1], af[mt][2], af[mt][3], b0, b1);
            }
        }
        __syncthreads();
    }

    // ---- epilogue ----
    const bool to_msg = (msg != nullptr) && (colBase == 0);
#pragma unroll
    for (int mt = 0; mt < 4; mt++) {
        int r0 = rowBase + wm + mt * 16 + g;
#pragma unroll
        for (int nt = 0; nt < 4; nt++) {
            int col = colBase + wn + nt * 8 + 2 * t4;
            if (to_msg) {
                if (r0 < M)
                    *(__nv_bfloat162*)(msg + (size_t)r0 * DH + col) =
                        __floats2bfloat162_rn(acc[mt][nt][0], acc[mt][nt][1]);
                if (r0 + 8 < M)
                    *(__nv_bfloat162*)(msg + (size_t)(r0 + 8) * DH + col) =
                        __floats2bfloat162_rn(acc[mt][nt][2], acc[mt][nt][3]);
            } else {
                if (r0 < M)
                    *(float2*)(C + (size_t)r0 * Ncol + col) =
                        make_float2(acc[mt][nt][0], acc[mt][nt][1]);
                if (r0 + 8 < M)
                    *(float2*)(C + (size_t)(r0 + 8) * Ncol + col) =
                        make_float2(acc[mt][nt][2], acc[mt][nt][3]);
            }
        }
    }
}

// ---------------- edge aggregation: 16 lanes per edge, bf16 ----------------
__global__ void edge_agg_bf16(const __nv_bfloat16* __restrict__ msg,
                              const int* __restrict__ src, const int* __restrict__ dst,
                              __nv_bfloat16* __restrict__ agg, int* __restrict__ deg, int E) {
    int gid = blockIdx.x * blockDim.x + threadIdx.x;
    int e = gid >> 4;
    int lane = gid & 15;
    if (e >= E) return;
    int s = src[e];
    int d = dst[e];
    uint4 v = *((const uint4*)(msg + (size_t)s * DH) + lane);
    uint32_t* a = (uint32_t*)(agg + (size_t)d * DH) + lane * 4;
    asm volatile("red.global.add.noftz.v4.bf16x2 [%0], {%1,%2,%3,%4};"
                 :: "l"(a), "r"(v.x), "r"(v.y), "r"(v.z), "r"(v.w) : "memory");
    if (deg != nullptr && lane == 0) atomicAdd(deg + d, 1);
}

// ---------------- node epilogue conv0 ----------------
// h1 = relu(agg1/deg + bl0 + r0) + (proj + bp)   r0 = C1[:,128:256], proj = C1[:,256:384]
__global__ void node0_kernel(const float* __restrict__ bl0, const float* __restrict__ bp, int N) {
    int idx = blockIdx.x * blockDim.x + threadIdx.x;
    if (idx >= N * 32) return;
    int i = idx >> 5, c = idx & 31;
    float dinv = 1.0f / fmaxf((float)g_deg[i], 1.0f);
    uint2 u = *(const uint2*)(g_agg1 + (size_t)i * DH + c * 4);
    float2 a01 = __bfloat1622float2(*reinterpret_cast<__nv_bfloat162*>(&u.x));
    float2 a23 = __bfloat1622float2(*reinterpret_cast<__nv_bfloat162*>(&u.y));
    float4 r  = *(const float4*)(g_C1 + (size_t)i * 384 + 128 + c * 4);
    float4 p  = *(const float4*)(g_C1 + (size_t)i * 384 + 256 + c * 4);
    float4 bl = *(const float4*)(bl0 + c * 4);
    float4 bv = *(const float4*)(bp + c * 4);
    float4 o;
    o.x = fmaxf(fmaf(a01.x, dinv, bl.x + r.x), 0.f) + p.x + bv.x;
    o.y = fmaxf(fmaf(a01.y, dinv, bl.y + r.y), 0.f) + p.y + bv.y;
    o.z = fmaxf(fmaf(a23.x, dinv, bl.z + r.z), 0.f) + p.z + bv.z;
    o.w = fmaxf(fmaf(a23.y, dinv, bl.w + r.w), 0.f) + p.w + bv.w;
    *(float4*)(g_h1 + (size_t)i * DH + c * 4) = o;
}

// ---------------- node epilogue conv1 ----------------
// h2 = relu(agg2/deg + bl1 + r1) + h1            r1 = C2[:,128:256]
__global__ void node1_kernel(const float* __restrict__ bl1, int N) {
    int idx = blockIdx.x * blockDim.x + threadIdx.x;
    if (idx >= N * 32) return;
    int i = idx >> 5, c = idx & 31;
    float dinv = 1.0f / fmaxf((float)g_deg[i], 1.0f);
    uint2 u = *(const uint2*)(g_agg2 + (size_t)i * DH + c * 4);
    float2 a01 = __bfloat1622float2(*reinterpret_cast<__nv_bfloat162*>(&u.x));
    float2 a23 = __bfloat1622float2(*reinterpret_cast<__nv_bfloat162*>(&u.y));
    float4 r  = *(const float4*)(g_C2 + (size_t)i * 256 + 128 + c * 4);
    float4 hp = *(const float4*)(g_h1 + (size_t)i * DH + c * 4);
    float4 bl = *(const float4*)(bl1 + c * 4);
    float4 o;
    o.x = fmaxf(fmaf(a01.x, dinv, bl.x + r.x), 0.f) + hp.x;
    o.y = fmaxf(fmaf(a01.y, dinv, bl.y + r.y), 0.f) + hp.y;
    o.z = fmaxf(fmaf(a23.x, dinv, bl.z + r.z), 0.f) + hp.z;
    o.w = fmaxf(fmaf(a23.y, dinv, bl.w + r.w), 0.f) + hp.w;
    *(float4*)(g_h2 + (size_t)i * DH + c * 4) = o;
}

// ---------------- fused MLP head + blend ----------------
__global__ __launch_bounds__(256)
void head_kernel(const float* __restrict__ W1, const float* __restrict__ b1,
                 const float* __restrict__ W2, const float* __restrict__ b2,
                 const float* __restrict__ rer, const float* __restrict__ alogit,
                 float* __restrict__ out, int N) {
    __shared__ float W1s[128 * 64];
    __shared__ float b1s[64];
    __shared__ float W2s[64];

    for (int k = threadIdx.x; k < 128 * 64; k += blockDim.x) W1s[k] = W1[k];
    if (threadIdx.x < 64) { b1s[threadIdx.x] = b1[threadIdx.x]; W2s[threadIdx.x] = W2[threadIdx.x]; }
    __syncthreads();

    int i = blockIdx.x * blockDim.x + threadIdx.x;
    if (i >= N) return;

    float acc[64];
#pragma unroll
    for (int j = 0; j < 64; j++) acc[j] = b1s[j];

    const float4* h4 = (const float4*)(g_h2 + (size_t)i * DH);
#pragma unroll 4
    for (int k4 = 0; k4 < 32; k4++) {
        float4 xv = h4[k4];
        float xs[4] = {xv.x, xv.y, xv.z, xv.w};
#pragma unroll
        for (int kk = 0; kk < 4; kk++) {
            float xk = xs[kk];
            int k = k4 * 4 + kk;
            const float4* wrow = (const float4*)&W1s[k * 64];
#pragma unroll
            for (int j4 = 0; j4 < 16; j4++) {
                float4 w = wrow[j4];
                acc[j4 * 4 + 0] = fmaf(xk, w.x, acc[j4 * 4 + 0]);
                acc[j4 * 4 + 1] = fmaf(xk, w.y, acc[j4 * 4 + 1]);
                acc[j4 * 4 + 2] = fmaf(xk, w.z, acc[j4 * 4 + 2]);
                acc[j4 * 4 + 3] = fmaf(xk, w.w, acc[j4 * 4 + 3]);
            }
        }
    }

    float s = b2[0];
#pragma unroll
    for (int j = 0; j < 64; j++) s = fmaf(fmaxf(acc[j], 0.f), W2s[j], s);

    float alpha = 1.0f / (1.0f + __expf(-alogit[0]));
    out[i] = alpha * rer[i] + (1.0f - alpha) * s;
}

// ---------------- launch ----------------
extern "C" void kernel_launch(void* const* d_in, const int* in_sizes, int n_in,
                              void* d_out, int out_size) {
    const float* x     = (const float*)d_in[0];
    const int*   eidx  = (const int*)d_in[1];
    const float* rer   = (const float*)d_in[2];
    const float* Wp    = (const float*)d_in[3];
    const float* bp    = (const float*)d_in[4];
    const float* Wl0   = (const float*)d_in[5];
    const float* bl0   = (const float*)d_in[6];
    const float* Wr0   = (const float*)d_in[7];
    const float* Wl1   = (const float*)d_in[8];
    const float* bl1   = (const float*)d_in[9];
    const float* Wr1   = (const float*)d_in[10];
    const float* W1    = (const float*)d_in[11];
    const float* b1    = (const float*)d_in[12];
    const float* W2    = (const float*)d_in[13];
    const float* b2    = (const float*)d_in[14];
    const float* alog  = (const float*)d_in[15];
    float* out = (float*)d_out;

    const int N = in_sizes[0] / DIN;       // 50000
    const int E = in_sizes[1] / 2;         // 800000
    const int* src = eidx;
    const int* dst = eidx + E;

    float *C1, *h1, *C2;
    __nv_bfloat16 *msg1, *msg2, *agg1, *agg2;
    int* deg;
    cudaGetSymbolAddress((void**)&C1,   g_C1);
    cudaGetSymbolAddress((void**)&h1,   g_h1);
    cudaGetSymbolAddress((void**)&C2,   g_C2);
    cudaGetSymbolAddress((void**)&msg1, g_msg1);
    cudaGetSymbolAddress((void**)&msg2, g_msg2);
    cudaGetSymbolAddress((void**)&agg1, g_agg1);
    cudaGetSymbolAddress((void**)&agg2, g_agg2);
    cudaGetSymbolAddress((void**)&deg,  g_deg);

    float *Bp1, *Bp2;
    cudaGetSymbolAddress((void**)&Bp1, g_Bp1);
    cudaGetSymbolAddress((void**)&Bp2, g_Bp2);
    (void)Bp1; (void)Bp2;

    // pack fused weight matrices
    pack_kernel<<<(DIN * 384 + 255) / 256, 256>>>(Wl0, Wr0, Wp, Wl1, Wr1);

    // zero both agg buffers (bf16) + degree, one launch
    int n16 = N * DH * 2 / 16;   // uint4 count per agg buffer
    zero_all<<<(n16 + 255) / 256, 256>>>(n16, N);

    // GEMM1: [N,256]@[256,384]; col block 0 -> bf16 msg1, blocks 1,2 -> fp32 C1
    {
        dim3 grid(384 / 128, (N + 127) / 128);
        gemm_tf32<<<grid, 256>>>(x, Bp1, C1, msg1, N, DIN, 384);
    }

    // conv0 edge aggregation (bf16), + degree
    {
        int blocks = (E * 16 + 255) / 256;
        edge_agg_bf16<<<blocks, 256>>>(msg1, src, dst, agg1, deg, E);
    }

    // h1 = relu(agg1/deg + bl0 + x@Wr0) + (x@Wp + bp)
    node0_kernel<<<(N * 32 + 255) / 256, 256>>>(bl0, bp, N);

    // GEMM2: [N,128]@[128,256]; col block 0 -> bf16 msg2, block 1 -> fp32 C2
    {
        dim3 grid(256 / 128, (N + 127) / 128);
        gemm_tf32<<<grid, 256>>>(h1, Bp2, C2, msg2, N, DH, 256);
    }

    // conv1 edge aggregation (bf16)
    {
        int blocks = (E * 16 + 255) / 256;
        edge_agg_bf16<<<blocks, 256>>>(msg2, src, dst, agg2, nullptr, E);
    }

    // h2 = relu(agg2/deg + bl1 + h1@Wr1) + h1
    node1_kernel<<<(N * 32 + 255) / 256, 256>>>(bl1, N);

    // MLP head + blend
    head_kernel<<<(N + 255) / 256, 256>>>(W1, b1, W2, b2, rer, alog, out, N);
}

// round 4
// speedup vs baseline: 2.2113x; 1.2523x over previous
#include <cuda_runtime.h>
#include <cuda_bf16.h>
#include <math.h>
#include <stdint.h>

#define NN   50000
#define EE   800000
#define DIN  256
#define DH   128

// ---------------- scratch (static device globals; no allocation) ----------------
__device__ __align__(16) float g_C1[(size_t)NN * 384];            // cols 128:384 used (fp32)
__device__ __align__(16) float g_C2[(size_t)NN * 256];            // cols 128:256 used (fp32)
__device__ __align__(16) float g_h1[(size_t)NN * DH];
__device__ __align__(16) float g_h2[(size_t)NN * DH];
__device__ __align__(16) __nv_bfloat16 g_xb [(size_t)NN * DIN];   // x in bf16
__device__ __align__(16) __nv_bfloat16 g_h1b[(size_t)NN * DH];    // h1 in bf16
__device__ __align__(16) __nv_bfloat16 g_msg1[(size_t)NN * DH];   // bf16 messages layer 0
__device__ __align__(16) __nv_bfloat16 g_msg2[(size_t)NN * DH];   // bf16 messages layer 1
__device__ int g_deg[NN];
__device__ int g_rowptr[NN + 1];
__device__ int g_cursor[NN];
__device__ int g_csr_src[EE];
__device__ __align__(16) uint32_t g_Bp1b[(DIN / 2) * 384];        // bf16 pairs [kpair][384]
__device__ __align__(16) uint32_t g_Bp2b[(DH / 2) * 256];         // bf16 pairs [kpair][256]

// ---------------- pack weights to bf16 k-pair layout + zero deg ----------------
__global__ void pack_kernel(const float* __restrict__ Wl0, const float* __restrict__ Wr0,
                            const float* __restrict__ Wp,
                            const float* __restrict__ Wl1, const float* __restrict__ Wr1) {
    int idx = blockIdx.x * blockDim.x + threadIdx.x;
    if (idx < (DIN / 2) * 384) {
        int kp = idx / 384, j = idx % 384;
        int k0 = 2 * kp, k1 = 2 * kp + 1;
        float lo, hi;
        if (j < 128)      { lo = Wl0[k0 * DH + j];        hi = Wl0[k1 * DH + j]; }
        else if (j < 256) { lo = Wr0[k0 * DH + j - 128];  hi = Wr0[k1 * DH + j - 128]; }
        else              { lo = Wp [k0 * DH + j - 256];  hi = Wp [k1 * DH + j - 256]; }
        __nv_bfloat162 p = __floats2bfloat162_rn(lo, hi);
        g_Bp1b[idx] = *reinterpret_cast<uint32_t*>(&p);
    }
    if (idx < (DH / 2) * 256) {
        int kp = idx / 256, j = idx % 256;
        int k0 = 2 * kp, k1 = 2 * kp + 1;
        float lo, hi;
        if (j < 128) { lo = Wl1[k0 * DH + j];       hi = Wl1[k1 * DH + j]; }
        else         { lo = Wr1[k0 * DH + j - 128]; hi = Wr1[k1 * DH + j - 128]; }
        __nv_bfloat162 p = __floats2bfloat162_rn(lo, hi);
        g_Bp2b[idx] = *reinterpret_cast<uint32_t*>(&p);
    }
    if (idx < NN) g_deg[idx] = 0;
}

// ---------------- x -> bf16 ----------------
__global__ void convert_x(const float* __restrict__ x, int nWords) {
    int i = blockIdx.x * blockDim.x + threadIdx.x;
    if (i >= nWords) return;
    float2 v = ((const float2*)x)[i];
    __nv_bfloat162 p = __floats2bfloat162_rn(v.x, v.y);
    ((uint32_t*)g_xb)[i] = *reinterpret_cast<uint32_t*>(&p);
}

// ---------------- CSR build ----------------
__global__ void hist_kernel(const int* __restrict__ dst, int E) {
    int e = blockIdx.x * blockDim.x + threadIdx.x;
    if (e < E) atomicAdd(&g_deg[dst[e]], 1);
}

__global__ void scan_kernel(int N) {
    __shared__ int warpsum[32];
    __shared__ int carry_s;
    if (threadIdx.x == 0) carry_s = 0;
    __syncthreads();
    int lane = threadIdx.x & 31, wid = threadIdx.x >> 5;
    for (int base = 0; base < N; base += 1024) {
        int idx = base + threadIdx.x;
        int v = (idx < N) ? g_deg[idx] : 0;
        int x = v;
#pragma unroll
        for (int o = 1; o < 32; o <<= 1) {
            int y = __shfl_up_sync(0xffffffffu, x, o);
            if (lane >= o) x += y;
        }
        if (lane == 31) warpsum[wid] = x;
        __syncthreads();
        if (wid == 0) {
            int s = warpsum[lane];
#pragma unroll
            for (int o = 1; o < 32; o <<= 1) {
                int y = __shfl_up_sync(0xffffffffu, s, o);
                if (lane >= o) s += y;
            }
            warpsum[lane] = s;
        }
        __syncthreads();
        int carry = carry_s;
        int excl = x - v + (wid > 0 ? warpsum[wid - 1] : 0) + carry;
        if (idx < N) { g_rowptr[idx] = excl; g_cursor[idx] = excl; }
        int bt = warpsum[31];
        __syncthreads();
        if (threadIdx.x == 0) carry_s = carry + bt;
        __syncthreads();
    }
    if (threadIdx.x == 0) g_rowptr[N] = carry_s;
}

__global__ void csr_fill(const int* __restrict__ src, const int* __restrict__ dst, int E) {
    int e = blockIdx.x * blockDim.x + threadIdx.x;
    if (e >= E) return;
    int slot = atomicAdd(&g_cursor[dst[e]], 1);
    g_csr_src[slot] = src[e];
}

// ---------------- bf16 tensor-core GEMM (m16n8k16), software-pipelined ----------------
// C[M,Ncol] = A[M,K] @ B[K,Ncol]. A: bf16 row-major. B: packed bf16 k-pairs
// [K/2][Ncol] uint32. Block tile 128x128, k-chunk 32, 8 warps = 2(M)x4(N).
// Column block at colBase==0 is written as bf16 into msg (row stride DH);
// other blocks as fp32 into C.

#define SPAD 136   // smem row stride in words: bank = (8*kp + m) % 32, conflict-free frags

__device__ __forceinline__ void mma_bf16(float c[4], uint32_t a0, uint32_t a1,
                                         uint32_t a2, uint32_t a3,
                                         uint32_t b0, uint32_t b1) {
    asm volatile(
        "mma.sync.aligned.m16n8k16.row.col.f32.bf16.bf16.f32 "
        "{%0,%1,%2,%3}, {%4,%5,%6,%7}, {%8,%9}, {%0,%1,%2,%3};"
        : "+f"(c[0]), "+f"(c[1]), "+f"(c[2]), "+f"(c[3])
        : "r"(a0), "r"(a1), "r"(a2), "r"(a3), "r"(b0), "r"(b1));
}

__global__ __launch_bounds__(256)
void gemm_bf16(const __nv_bfloat16* __restrict__ A, const uint32_t* __restrict__ Bp,
               float* __restrict__ C, __nv_bfloat16* __restrict__ msg,
               int M, int K, int Ncol) {
    __shared__ uint32_t As[16][SPAD];   // [kpair][m]
    __shared__ uint32_t Bs[16][SPAD];   // [kpair][n]

    const int t = threadIdx.x;
    const int lane = t & 31;
    const int warp = t >> 5;
    const int wm = (warp & 1) * 64;
    const int wn = (warp >> 1) * 32;
    const int g = lane >> 2;
    const int t4 = lane & 3;

    const int rowBase = blockIdx.y * 128;
    const int colBase = blockIdx.x * 128;

    // A staging: thread -> row (t&127), k-half (t>>7)*16 bf16
    const int ar = t & 127;
    const int ah = t >> 7;          // 0 or 1
    // B staging: thread -> kpair (t>>4), col (t&15)*8
    const int bkp = t >> 4;         // 0..15
    const int bcol = (t & 15) * 8;

    float acc[4][4][4];
#pragma unroll
    for (int mt = 0; mt < 4; mt++)
#pragma unroll
        for (int nt = 0; nt < 4; nt++)
#pragma unroll
            for (int i = 0; i < 4; i++) acc[mt][nt][i] = 0.f;

    const int grow = rowBase + ar;
    const bool arow_ok = (grow < M);
    const __nv_bfloat16* aBase = A + (size_t)grow * K + ah * 16;
    const uint32_t* bBase = Bp + (size_t)bkp * Ncol + colBase + bcol;

    uint4 ra0, ra1, rb0, rb1;

    // preload chunk 0
    if (arow_ok) {
        ra0 = *(const uint4*)(aBase);
        ra1 = *(const uint4*)(aBase + 8);
    } else {
        ra0 = make_uint4(0, 0, 0, 0); ra1 = make_uint4(0, 0, 0, 0);
    }
    rb0 = *(const uint4*)(bBase);
    rb1 = *(const uint4*)(bBase + 4);

    const int nChunks = K >> 5;
    for (int ci = 0; ci < nChunks; ci++) {
        // store current chunk to smem
        {
            const int kb = ah * 8;
            As[kb + 0][ar] = ra0.x; As[kb + 1][ar] = ra0.y;
            As[kb + 2][ar] = ra0.z; As[kb + 3][ar] = ra0.w;
            As[kb + 4][ar] = ra1.x; As[kb + 5][ar] = ra1.y;
            As[kb + 6][ar] = ra1.z; As[kb + 7][ar] = ra1.w;
            *(uint4*)&Bs[bkp][bcol]     = rb0;
            *(uint4*)&Bs[bkp][bcol + 4] = rb1;
        }
        __syncthreads();

        // preload next chunk
        if (ci + 1 < nChunks) {
            int k0 = (ci + 1) << 5;
            if (arow_ok) {
                ra0 = *(const uint4*)(aBase + k0);
                ra1 = *(const uint4*)(aBase + k0 + 8);
            }
            rb0 = *(const uint4*)(bBase + (size_t)(k0 >> 1) * Ncol);
            rb1 = *(const uint4*)(bBase + (size_t)(k0 >> 1) * Ncol + 4);
        }

        // compute: 2 k16 steps
#pragma unroll
        for (int kk = 0; kk < 2; kk++) {
            const int kb = kk * 8;
            uint32_t af[4][4];
#pragma unroll
            for (int mt = 0; mt < 4; mt++) {
                int r = wm + mt * 16 + g;
                af[mt][0] = As[kb + t4][r];
                af[mt][1] = As[kb + t4][r + 8];
                af[mt][2] = As[kb + t4 + 4][r];
                af[mt][3] = As[kb + t4 + 4][r + 8];
            }
#pragma unroll
            for (int nt = 0; nt < 4; nt++) {
                int cn = wn + nt * 8 + g;
                uint32_t b0 = Bs[kb + t4][cn];
                uint32_t b1 = Bs[kb + t4 + 4][cn];
#pragma unroll
                for (int mt = 0; mt < 4; mt++)
                    mma_bf16(acc[mt][nt], af[mt][0], af[mt][1], af[mt][2], af[mt][3], b0, b1);
            }
        }
        __syncthreads();
    }

    // epilogue: c0,c1 -> (g, 2t4), c2,c3 -> (g+8, 2t4)
    const bool to_msg = (msg != nullptr) && (colBase == 0);
#pragma unroll
    for (int mt = 0; mt < 4; mt++) {
        int r0 = rowBase + wm + mt * 16 + g;
#pragma unroll
        for (int nt = 0; nt < 4; nt++) {
            int col = colBase + wn + nt * 8 + 2 * t4;
            if (to_msg) {
                if (r0 < M)
                    *(__nv_bfloat162*)(msg + (size_t)r0 * DH + col) =
                        __floats2bfloat162_rn(acc[mt][nt][0], acc[mt][nt][1]);
                if (r0 + 8 < M)
                    *(__nv_bfloat162*)(msg + (size_t)(r0 + 8) * DH + col) =
                        __floats2bfloat162_rn(acc[mt][nt][2], acc[mt][nt][3]);
            } else {
                if (r0 < M)
                    *(float2*)(C + (size_t)r0 * Ncol + col) =
                        make_float2(acc[mt][nt][0], acc[mt][nt][1]);
                if (r0 + 8 < M)
                    *(float2*)(C + (size_t)(r0 + 8) * Ncol + col) =
                        make_float2(acc[mt][nt][2], acc[mt][nt][3]);
            }
        }
    }
}

// ---------------- fused pull-aggregation + node epilogue, layer 0 ----------------
// warp per node: acc = sum_{j in N(i)} msg1[src_j]  (fp32 accum of bf16 rows)
// h1 = relu(acc/deg + bl0 + C1[:,128:256]) + C1[:,256:384] + bp ; also h1 bf16
__global__ __launch_bounds__(256)
void agg0_kernel(const float* __restrict__ bl0, const float* __restrict__ bp, int N) {
    int w = (blockIdx.x * blockDim.x + threadIdx.x) >> 5;
    int lane = threadIdx.x & 31;
    if (w >= N) return;
    int nbeg = g_rowptr[w], nend = g_rowptr[w + 1];
    float a0 = 0.f, a1 = 0.f, a2 = 0.f, a3 = 0.f;
    int j = nbeg;
    for (; j + 4 <= nend; j += 4) {
        int s0 = g_csr_src[j], s1 = g_csr_src[j + 1], s2 = g_csr_src[j + 2], s3 = g_csr_src[j + 3];
        uint2 v0 = *((const uint2*)(g_msg1 + (size_t)s0 * DH) + lane);
        uint2 v1 = *((const uint2*)(g_msg1 + (size_t)s1 * DH) + lane);
        uint2 v2 = *((const uint2*)(g_msg1 + (size_t)s2 * DH) + lane);
        uint2 v3 = *((const uint2*)(g_msg1 + (size_t)s3 * DH) + lane);
        float2 p;
        p = __bfloat1622float2(*reinterpret_cast<__nv_bfloat162*>(&v0.x)); a0 += p.x; a1 += p.y;
        p = __bfloat1622float2(*reinterpret_cast<__nv_bfloat162*>(&v0.y)); a2 += p.x; a3 += p.y;
        p = __bfloat1622float2(*reinterpret_cast<__nv_bfloat162*>(&v1.x)); a0 += p.x; a1 += p.y;
        p = __bfloat1622float2(*reinterpret_cast<__nv_bfloat162*>(&v1.y)); a2 += p.x; a3 += p.y;
        p = __bfloat1622float2(*reinterpret_cast<__nv_bfloat162*>(&v2.x)); a0 += p.x; a1 += p.y;
        p = __bfloat1622float2(*reinterpret_cast<__nv_bfloat162*>(&v2.y)); a2 += p.x; a3 += p.y;
        p = __bfloat1622float2(*reinterpret_cast<__nv_bfloat162*>(&v3.x)); a0 += p.x; a1 += p.y;
        p = __bfloat1622float2(*reinterpret_cast<__nv_bfloat162*>(&v3.y)); a2 += p.x; a3 += p.y;
    }
    for (; j < nend; j++) {
        int s = g_csr_src[j];
        uint2 v = *((const uint2*)(g_msg1 + (size_t)s * DH) + lane);
        float2 p;
        p = __bfloat1622float2(*reinterpret_cast<__nv_bfloat162*>(&v.x)); a0 += p.x; a1 += p.y;
        p = __bfloat1622float2(*reinterpret_cast<__nv_bfloat162*>(&v.y)); a2 += p.x; a3 += p.y;
    }
    float dinv = 1.0f / fmaxf((float)(nend - nbeg), 1.0f);
    float4 r  = *(const float4*)(g_C1 + (size_t)w * 384 + 128 + lane * 4);
    float4 pj = *(const float4*)(g_C1 + (size_t)w * 384 + 256 + lane * 4);
    float4 bl = *(const float4*)(bl0 + lane * 4);
    float4 bv = *(const float4*)(bp + lane * 4);
    float4 o;
    o.x = fmaxf(fmaf(a0, dinv, bl.x + r.x), 0.f) + pj.x + bv.x;
    o.y = fmaxf(fmaf(a1, dinv, bl.y + r.y), 0.f) + pj.y + bv.y;
    o.z = fmaxf(fmaf(a2, dinv, bl.z + r.z), 0.f) + pj.z + bv.z;
    o.w = fmaxf(fmaf(a3, dinv, bl.w + r.w), 0.f) + pj.w + bv.w;
    *(float4*)(g_h1 + (size_t)w * DH + lane * 4) = o;
    __nv_bfloat162 q0 = __floats2bfloat162_rn(o.x, o.y);
    __nv_bfloat162 q1 = __floats2bfloat162_rn(o.z, o.w);
    uint2 qo; qo.x = *reinterpret_cast<uint32_t*>(&q0); qo.y = *reinterpret_cast<uint32_t*>(&q1);
    *((uint2*)(g_h1b + (size_t)w * DH) + lane) = qo;
}

// ---------------- fused pull-aggregation + node epilogue, layer 1 ----------------
// h2 = relu(acc/deg + bl1 + C2[:,128:256]) + h1
__global__ __launch_bounds__(256)
void agg1_kernel(const float* __restrict__ bl1, int N) {
    int w = (blockIdx.x * blockDim.x + threadIdx.x) >> 5;
    int lane = threadIdx.x & 31;
    if (w >= N) return;
    int nbeg = g_rowptr[w], nend = g_rowptr[w + 1];
    float a0 = 0.f, a1 = 0.f, a2 = 0.f, a3 = 0.f;
    int j = nbeg;
    for (; j + 4 <= nend; j += 4) {
        int s0 = g_csr_src[j], s1 = g_csr_src[j + 1], s2 = g_csr_src[j + 2], s3 = g_csr_src[j + 3];
        uint2 v0 = *((const uint2*)(g_msg2 + (size_t)s0 * DH) + lane);
        uint2 v1 = *((const uint2*)(g_msg2 + (size_t)s1 * DH) + lane);
        uint2 v2 = *((const uint2*)(g_msg2 + (size_t)s2 * DH) + lane);
        uint2 v3 = *((const uint2*)(g_msg2 + (size_t)s3 * DH) + lane);
        float2 p;
        p = __bfloat1622float2(*reinterpret_cast<__nv_bfloat162*>(&v0.x)); a0 += p.x; a1 += p.y;
        p = __bfloat1622float2(*reinterpret_cast<__nv_bfloat162*>(&v0.y)); a2 += p.x; a3 += p.y;
        p = __bfloat1622float2(*reinterpret_cast<__nv_bfloat162*>(&v1.x)); a0 += p.x; a1 += p.y;
        p = __bfloat1622float2(*reinterpret_cast<__nv_bfloat162*>(&v1.y)); a2 += p.x; a3 += p.y;
        p = __bfloat1622float2(*reinterpret_cast<__nv_bfloat162*>(&v2.x)); a0 += p.x; a1 += p.y;
        p = __bfloat1622float2(*reinterpret_cast<__nv_bfloat162*>(&v2.y)); a2 += p.x; a3 += p.y;
        p = __bfloat1622float2(*reinterpret_cast<__nv_bfloat162*>(&v3.x)); a0 += p.x; a1 += p.y;
        p = __bfloat1622float2(*reinterpret_cast<__nv_bfloat162*>(&v3.y)); a2 += p.x; a3 += p.y;
    }
    for (; j < nend; j++) {
        int s = g_csr_src[j];
        uint2 v = *((const uint2*)(g_msg2 + (size_t)s * DH) + lane);
        float2 p;
        p = __bfloat1622float2(*reinterpret_cast<__nv_bfloat162*>(&v.x)); a0 += p.x; a1 += p.y;
        p = __bfloat1622float2(*reinterpret_cast<__nv_bfloat162*>(&v.y)); a2 += p.x; a3 += p.y;
    }
    float dinv = 1.0f / fmaxf((float)(nend - nbeg), 1.0f);
    float4 r  = *(const float4*)(g_C2 + (size_t)w * 256 + 128 + lane * 4);
    float4 hp = *(const float4*)(g_h1 + (size_t)w * DH + lane * 4);
    float4 bl = *(const float4*)(bl1 + lane * 4);
    float4 o;
    o.x = fmaxf(fmaf(a0, dinv, bl.x + r.x), 0.f) + hp.x;
    o.y = fmaxf(fmaf(a1, dinv, bl.y + r.y), 0.f) + hp.y;
    o.z = fmaxf(fmaf(a2, dinv, bl.z + r.z), 0.f) + hp.z;
    o.w = fmaxf(fmaf(a3, dinv, bl.w + r.w), 0.f) + hp.w;
    *(float4*)(g_h2 + (size_t)w * DH + lane * 4) = o;
}

// ---------------- fused MLP head + blend ----------------
__global__ __launch_bounds__(256)
void head_kernel(const float* __restrict__ W1, const float* __restrict__ b1,
                 const float* __restrict__ W2, const float* __restrict__ b2,
                 const float* __restrict__ rer, const float* __restrict__ alogit,
                 float* __restrict__ out, int N) {
    __shared__ float W1s[128 * 64];
    __shared__ float b1s[64];
    __shared__ float W2s[64];

    for (int k = threadIdx.x; k < 128 * 64; k += blockDim.x) W1s[k] = W1[k];
    if (threadIdx.x < 64) { b1s[threadIdx.x] = b1[threadIdx.x]; W2s[threadIdx.x] = W2[threadIdx.x]; }
    __syncthreads();

    int i = blockIdx.x * blockDim.x + threadIdx.x;
    if (i >= N) return;

    float acc[64];
#pragma unroll
    for (int j = 0; j < 64; j++) acc[j] = b1s[j];

    const float4* h4 = (const float4*)(g_h2 + (size_t)i * DH);
#pragma unroll 4
    for (int k4 = 0; k4 < 32; k4++) {
        float4 xv = h4[k4];
        float xs[4] = {xv.x, xv.y, xv.z, xv.w};
#pragma unroll
        for (int kk = 0; kk < 4; kk++) {
            float xk = xs[kk];
            int k = k4 * 4 + kk;
            const float4* wrow = (const float4*)&W1s[k * 64];
#pragma unroll
            for (int j4 = 0; j4 < 16; j4++) {
                float4 w = wrow[j4];
                acc[j4 * 4 + 0] = fmaf(xk, w.x, acc[j4 * 4 + 0]);
                acc[j4 * 4 + 1] = fmaf(xk, w.y, acc[j4 * 4 + 1]);
                acc[j4 * 4 + 2] = fmaf(xk, w.z, acc[j4 * 4 + 2]);
                acc[j4 * 4 + 3] = fmaf(xk, w.w, acc[j4 * 4 + 3]);
            }
        }
    }

    float s = b2[0];
#pragma unroll
    for (int j = 0; j < 64; j++) s = fmaf(fmaxf(acc[j], 0.f), W2s[j], s);

    float alpha = 1.0f / (1.0f + __expf(-alogit[0]));
    out[i] = alpha * rer[i] + (1.0f - alpha) * s;
}

// ---------------- launch ----------------
extern "C" void kernel_launch(void* const* d_in, const int* in_sizes, int n_in,
                              void* d_out, int out_size) {
    const float* x     = (const float*)d_in[0];
    const int*   eidx  = (const int*)d_in[1];
    const float* rer   = (const float*)d_in[2];
    const float* Wp    = (const float*)d_in[3];
    const float* bp    = (const float*)d_in[4];
    const float* Wl0   = (const float*)d_in[5];
    const float* bl0   = (const float*)d_in[6];
    const float* Wr0   = (const float*)d_in[7];
    const float* Wl1   = (const float*)d_in[8];
    const float* bl1   = (const float*)d_in[9];
    const float* Wr1   = (const float*)d_in[10];
    const float* W1    = (const float*)d_in[11];
    const float* b1    = (const float*)d_in[12];
    const float* W2    = (const float*)d_in[13];
    const float* b2    = (const float*)d_in[14];
    const float* alog  = (const float*)d_in[15];
    float* out = (float*)d_out;

    const int N = in_sizes[0] / DIN;       // 50000
    const int E = in_sizes[1] / 2;         // 800000
    const int* src = eidx;
    const int* dst = eidx + E;

    float *C1, *C2;
    __nv_bfloat16 *xb, *h1b, *msg1, *msg2;
    uint32_t *Bp1b, *Bp2b;
    cudaGetSymbolAddress((void**)&C1,   g_C1);
    cudaGetSymbolAddress((void**)&C2,   g_C2);
    cudaGetSymbolAddress((void**)&xb,   g_xb);
    cudaGetSymbolAddress((void**)&h1b,  g_h1b);
    cudaGetSymbolAddress((void**)&msg1, g_msg1);
    cudaGetSymbolAddress((void**)&msg2, g_msg2);
    cudaGetSymbolAddress((void**)&Bp1b, g_Bp1b);
    cudaGetSymbolAddress((void**)&Bp2b, g_Bp2b);

    // pack weights (bf16 pairs) + zero deg
    {
        int nthr = (DIN / 2) * 384;            // 49152; also covers NN via grid size
        int grid = (max(nthr, N) + 255) / 256;
        pack_kernel<<<grid, 256>>>(Wl0, Wr0, Wp, Wl1, Wr1);
    }

    // x -> bf16
    {
        int nWords = N * DIN / 2;
        convert_x<<<(nWords + 255) / 256, 256>>>(x, nWords);
    }

    // CSR build: histogram -> scan -> fill
    hist_kernel<<<(E + 255) / 256, 256>>>(dst, E);
    scan_kernel<<<1, 1024>>>(N);
    csr_fill<<<(E + 255) / 256, 256>>>(src, dst, E);

    // GEMM1: xb[N,256] @ Bp1b -> msg1 (bf16, block 0) + C1 (fp32, blocks 1,2)
    {
        dim3 grid(384 / 128, (N + 127) / 128);
        gemm_bf16<<<grid, 256>>>(xb, Bp1b, C1, msg1, N, DIN, 384);
    }

    // pull-agg layer 0 + epilogue -> h1 (fp32 + bf16)
    agg0_kernel<<<(N * 32 + 255) / 256, 256>>>(bl0, bp, N);

    // GEMM2: h1b[N,128] @ Bp2b -> msg2 (bf16, block 0) + C2 (fp32, block 1)
    {
        dim3 grid(256 / 128, (N + 127) / 128);
        gemm_bf16<<<grid, 256>>>(h1b, Bp2b, C2, msg2, N, DH, 256);
    }

    // pull-agg layer 1 + epilogue -> h2
    agg1_kernel<<<(N * 32 + 255) / 256, 256>>>(bl1, N);

    // MLP head + blend
    head_kernel<<<(N + 255) / 256, 256>>>(W1, b1, W2, b2, rer, alog, out, N);
}

// round 5
// speedup vs baseline: 2.5296x; 1.1439x over previous
#include <cuda_runtime.h>
#include <cuda_bf16.h>
#include <math.h>
#include <stdint.h>

#define NN   50000
#define EE   800000
#define DIN  256
#define DH   128
#define NBLK ((NN + 1023) / 1024)   // 49 scan blocks

// ---------------- scratch (static device globals; no allocation) ----------------
__device__ __align__(16) float g_C1[(size_t)NN * 384];            // cols 128:384 used (fp32)
__device__ __align__(16) float g_C2[(size_t)NN * 256];            // cols 128:256 used (fp32)
__device__ __align__(16) float g_h1[(size_t)NN * DH];
__device__ __align__(16) float g_h2[(size_t)NN * DH];
__device__ __align__(16) __nv_bfloat16 g_xb [(size_t)NN * DIN];   // x in bf16
__device__ __align__(16) __nv_bfloat16 g_h1b[(size_t)NN * DH];    // h1 in bf16
__device__ __align__(16) __nv_bfloat16 g_msg1[(size_t)NN * DH];   // bf16 messages layer 0
__device__ __align__(16) __nv_bfloat16 g_msg2[(size_t)NN * DH];   // bf16 messages layer 1
__device__ int g_deg[NN];
__device__ int g_rowptr[NN + 1];
__device__ int g_cursor[NN];
__device__ int g_csr_src[EE];
__device__ int g_bsum[64];
__device__ int g_boff[64];
__device__ __align__(16) uint32_t g_Bp1b[(DIN / 2) * 384];        // bf16 pairs [kpair][384]
__device__ __align__(16) uint32_t g_Bp2b[(DH / 2) * 256];         // bf16 pairs [kpair][256]

// ---------------- pack weights to bf16 k-pair layout + zero deg ----------------
__global__ void pack_kernel(const float* __restrict__ Wl0, const float* __restrict__ Wr0,
                            const float* __restrict__ Wp,
                            const float* __restrict__ Wl1, const float* __restrict__ Wr1) {
    int idx = blockIdx.x * blockDim.x + threadIdx.x;
    if (idx < (DIN / 2) * 384) {
        int kp = idx / 384, j = idx % 384;
        int k0 = 2 * kp, k1 = 2 * kp + 1;
        float lo, hi;
        if (j < 128)      { lo = Wl0[k0 * DH + j];        hi = Wl0[k1 * DH + j]; }
        else if (j < 256) { lo = Wr0[k0 * DH + j - 128];  hi = Wr0[k1 * DH + j - 128]; }
        else              { lo = Wp [k0 * DH + j - 256];  hi = Wp [k1 * DH + j - 256]; }
        __nv_bfloat162 p = __floats2bfloat162_rn(lo, hi);
        g_Bp1b[idx] = *reinterpret_cast<uint32_t*>(&p);
    }
    if (idx < (DH / 2) * 256) {
        int kp = idx / 256, j = idx % 256;
        int k0 = 2 * kp, k1 = 2 * kp + 1;
        float lo, hi;
        if (j < 128) { lo = Wl1[k0 * DH + j];       hi = Wl1[k1 * DH + j]; }
        else         { lo = Wr1[k0 * DH + j - 128]; hi = Wr1[k1 * DH + j - 128]; }
        __nv_bfloat162 p = __floats2bfloat162_rn(lo, hi);
        g_Bp2b[idx] = *reinterpret_cast<uint32_t*>(&p);
    }
    if (idx < NN) g_deg[idx] = 0;
}

// ---------------- x -> bf16  +  degree histogram (merged) ----------------
__global__ void prep_kernel(const float* __restrict__ x, const int* __restrict__ dst,
                            int nWords, int E) {
    int i = blockIdx.x * blockDim.x + threadIdx.x;
    if (i < nWords) {
        float2 v = ((const float2*)x)[i];
        __nv_bfloat162 p = __floats2bfloat162_rn(v.x, v.y);
        ((uint32_t*)g_xb)[i] = *reinterpret_cast<uint32_t*>(&p);
    }
    if (i < E) atomicAdd(&g_deg[dst[i]], 1);
}

// ---------------- multi-block exclusive scan ----------------
__global__ __launch_bounds__(1024)
void scan_blocks(int N) {
    __shared__ int wsum[32];
    int lane = threadIdx.x & 31, wid = threadIdx.x >> 5;
    int idx = blockIdx.x * 1024 + threadIdx.x;
    int v = (idx < N) ? g_deg[idx] : 0;
    int x = v;
#pragma unroll
    for (int o = 1; o < 32; o <<= 1) {
        int y = __shfl_up_sync(0xffffffffu, x, o);
        if (lane >= o) x += y;
    }
    if (lane == 31) wsum[wid] = x;
    __syncthreads();
    if (wid == 0) {
        int s = wsum[lane];
#pragma unroll
        for (int o = 1; o < 32; o <<= 1) {
            int y = __shfl_up_sync(0xffffffffu, s, o);
            if (lane >= o) s += y;
        }
        wsum[lane] = s;
    }
    __syncthreads();
    int excl = x - v + (wid > 0 ? wsum[wid - 1] : 0);
    if (idx < N) g_rowptr[idx] = excl;
    if (threadIdx.x == 1023) g_bsum[blockIdx.x] = excl + v;
}

__global__ __launch_bounds__(64)
void scan_tops(int nb, int N) {
    __shared__ int wsum[2];
    int t = threadIdx.x;
    int lane = t & 31, wid = t >> 5;
    int v = (t < nb) ? g_bsum[t] : 0;
    int x = v;
#pragma unroll
    for (int o = 1; o < 32; o <<= 1) {
        int y = __shfl_up_sync(0xffffffffu, x, o);
        if (lane >= o) x += y;
    }
    if (lane == 31) wsum[wid] = x;
    __syncthreads();
    int excl = x - v + (wid > 0 ? wsum[0] : 0);
    if (t < nb) g_boff[t] = excl;
    if (t == nb - 1) g_rowptr[N] = excl + v;
}

__global__ void scan_add(int N) {
    int i = blockIdx.x * blockDim.x + threadIdx.x;
    if (i >= N) return;
    int r = g_rowptr[i] + g_boff[i >> 10];
    g_rowptr[i] = r;
    g_cursor[i] = r;
}

__global__ void csr_fill(const int* __restrict__ src, const int* __restrict__ dst, int E) {
    int e = blockIdx.x * blockDim.x + threadIdx.x;
    if (e >= E) return;
    int slot = atomicAdd(&g_cursor[dst[e]], 1);
    g_csr_src[slot] = src[e];
}

// ---------------- bf16 tensor-core GEMM (m16n8k16), software-pipelined ----------------
#define SPAD 136

__device__ __forceinline__ void mma_bf16(float c[4], uint32_t a0, uint32_t a1,
                                         uint32_t a2, uint32_t a3,
                                         uint32_t b0, uint32_t b1) {
    asm volatile(
        "mma.sync.aligned.m16n8k16.row.col.f32.bf16.bf16.f32 "
        "{%0,%1,%2,%3}, {%4,%5,%6,%7}, {%8,%9}, {%0,%1,%2,%3};"
        : "+f"(c[0]), "+f"(c[1]), "+f"(c[2]), "+f"(c[3])
        : "r"(a0), "r"(a1), "r"(a2), "r"(a3), "r"(b0), "r"(b1));
}

__global__ __launch_bounds__(256)
void gemm_bf16(const __nv_bfloat16* __restrict__ A, const uint32_t* __restrict__ Bp,
               float* __restrict__ C, __nv_bfloat16* __restrict__ msg,
               int M, int K, int Ncol) {
    __shared__ uint32_t As[16][SPAD];   // [kpair][m]
    __shared__ uint32_t Bs[16][SPAD];   // [kpair][n]

    const int t = threadIdx.x;
    const int lane = t & 31;
    const int warp = t >> 5;
    const int wm = (warp & 1) * 64;
    const int wn = (warp >> 1) * 32;
    const int g = lane >> 2;
    const int t4 = lane & 3;

    const int rowBase = blockIdx.y * 128;
    const int colBase = blockIdx.x * 128;

    const int ar = t & 127;
    const int ah = t >> 7;
    const int bkp = t >> 4;
    const int bcol = (t & 15) * 8;

    float acc[4][4][4];
#pragma unroll
    for (int mt = 0; mt < 4; mt++)
#pragma unroll
        for (int nt = 0; nt < 4; nt++)
#pragma unroll
            for (int i = 0; i < 4; i++) acc[mt][nt][i] = 0.f;

    const int grow = rowBase + ar;
    const bool arow_ok = (grow < M);
    const __nv_bfloat16* aBase = A + (size_t)grow * K + ah * 16;
    const uint32_t* bBase = Bp + (size_t)bkp * Ncol + colBase + bcol;

    uint4 ra0, ra1, rb0, rb1;

    if (arow_ok) {
        ra0 = *(const uint4*)(aBase);
        ra1 = *(const uint4*)(aBase + 8);
    } else {
        ra0 = make_uint4(0, 0, 0, 0); ra1 = make_uint4(0, 0, 0, 0);
    }
    rb0 = *(const uint4*)(bBase);
    rb1 = *(const uint4*)(bBase + 4);

    const int nChunks = K >> 5;
    for (int ci = 0; ci < nChunks; ci++) {
        {
            const int kb = ah * 8;
            As[kb + 0][ar] = ra0.x; As[kb + 1][ar] = ra0.y;
            As[kb + 2][ar] = ra0.z; As[kb + 3][ar] = ra0.w;
            As[kb + 4][ar] = ra1.x; As[kb + 5][ar] = ra1.y;
            As[kb + 6][ar] = ra1.z; As[kb + 7][ar] = ra1.w;
            *(uint4*)&Bs[bkp][bcol]     = rb0;
            *(uint4*)&Bs[bkp][bcol + 4] = rb1;
        }
        __syncthreads();

        if (ci + 1 < nChunks) {
            int k0 = (ci + 1) << 5;
            if (arow_ok) {
                ra0 = *(const uint4*)(aBase + k0);
                ra1 = *(const uint4*)(aBase + k0 + 8);
            }
            rb0 = *(const uint4*)(bBase + (size_t)(k0 >> 1) * Ncol);
            rb1 = *(const uint4*)(bBase + (size_t)(k0 >> 1) * Ncol + 4);
        }

#pragma unroll
        for (int kk = 0; kk < 2; kk++) {
            const int kb = kk * 8;
            uint32_t af[4][4];
#pragma unroll
            for (int mt = 0; mt < 4; mt++) {
                int r = wm + mt * 16 + g;
                af[mt][0] = As[kb + t4][r];
                af[mt][1] = As[kb + t4][r + 8];
                af[mt][2] = As[kb + t4 + 4][r];
                af[mt][3] = As[kb + t4 + 4][r + 8];
            }
#pragma unroll
            for (int nt = 0; nt < 4; nt++) {
                int cn = wn + nt * 8 + g;
                uint32_t b0 = Bs[kb + t4][cn];
                uint32_t b1 = Bs[kb + t4 + 4][cn];
#pragma unroll
                for (int mt = 0; mt < 4; mt++)
                    mma_bf16(acc[mt][nt], af[mt][0], af[mt][1], af[mt][2], af[mt][3], b0, b1);
            }
        }
        __syncthreads();
    }

    const bool to_msg = (msg != nullptr) && (colBase == 0);
#pragma unroll
    for (int mt = 0; mt < 4; mt++) {
        int r0 = rowBase + wm + mt * 16 + g;
#pragma unroll
        for (int nt = 0; nt < 4; nt++) {
            int col = colBase + wn + nt * 8 + 2 * t4;
            if (to_msg) {
                if (r0 < M)
                    *(__nv_bfloat162*)(msg + (size_t)r0 * DH + col) =
                        __floats2bfloat162_rn(acc[mt][nt][0], acc[mt][nt][1]);
                if (r0 + 8 < M)
                    *(__nv_bfloat162*)(msg + (size_t)(r0 + 8) * DH + col) =
                        __floats2bfloat162_rn(acc[mt][nt][2], acc[mt][nt][3]);
            } else {
                if (r0 < M)
                    *(float2*)(C + (size_t)r0 * Ncol + col) =
                        make_float2(acc[mt][nt][0], acc[mt][nt][1]);
                if (r0 + 8 < M)
                    *(float2*)(C + (size_t)(r0 + 8) * Ncol + col) =
                        make_float2(acc[mt][nt][2], acc[mt][nt][3]);
            }
        }
    }
}

// ---------------- fused pull-aggregation + node epilogue, layer 0 ----------------
__global__ __launch_bounds__(256)
void agg0_kernel(const float* __restrict__ bl0, const float* __restrict__ bp, int N) {
    int w = (blockIdx.x * blockDim.x + threadIdx.x) >> 5;
    int lane = threadIdx.x & 31;
    if (w >= N) return;
    int nbeg = g_rowptr[w], nend = g_rowptr[w + 1];
    float a0 = 0.f, a1 = 0.f, a2 = 0.f, a3 = 0.f;
    int j = nbeg;
    for (; j + 4 <= nend; j += 4) {
        int s0 = g_csr_src[j], s1 = g_csr_src[j + 1], s2 = g_csr_src[j + 2], s3 = g_csr_src[j + 3];
        uint2 v0 = *((const uint2*)(g_msg1 + (size_t)s0 * DH) + lane);
        uint2 v1 = *((const uint2*)(g_msg1 + (size_t)s1 * DH) + lane);
        uint2 v2 = *((const uint2*)(g_msg1 + (size_t)s2 * DH) + lane);
        uint2 v3 = *((const uint2*)(g_msg1 + (size_t)s3 * DH) + lane);
        float2 p;
        p = __bfloat1622float2(*reinterpret_cast<__nv_bfloat162*>(&v0.x)); a0 += p.x; a1 += p.y;
        p = __bfloat1622float2(*reinterpret_cast<__nv_bfloat162*>(&v0.y)); a2 += p.x; a3 += p.y;
        p = __bfloat1622float2(*reinterpret_cast<__nv_bfloat162*>(&v1.x)); a0 += p.x; a1 += p.y;
        p = __bfloat1622float2(*reinterpret_cast<__nv_bfloat162*>(&v1.y)); a2 += p.x; a3 += p.y;
        p = __bfloat1622float2(*reinterpret_cast<__nv_bfloat162*>(&v2.x)); a0 += p.x; a1 += p.y;
        p = __bfloat1622float2(*reinterpret_cast<__nv_bfloat162*>(&v2.y)); a2 += p.x; a3 += p.y;
        p = __bfloat1622float2(*reinterpret_cast<__nv_bfloat162*>(&v3.x)); a0 += p.x; a1 += p.y;
        p = __bfloat1622float2(*reinterpret_cast<__nv_bfloat162*>(&v3.y)); a2 += p.x; a3 += p.y;
    }
    for (; j < nend; j++) {
        int s = g_csr_src[j];
        uint2 v = *((const uint2*)(g_msg1 + (size_t)s * DH) + lane);
        float2 p;
        p = __bfloat1622float2(*reinterpret_cast<__nv_bfloat162*>(&v.x)); a0 += p.x; a1 += p.y;
        p = __bfloat1622float2(*reinterpret_cast<__nv_bfloat162*>(&v.y)); a2 += p.x; a3 += p.y;
    }
    float dinv = 1.0f / fmaxf((float)(nend - nbeg), 1.0f);
    float4 r  = *(const float4*)(g_C1 + (size_t)w * 384 + 128 + lane * 4);
    float4 pj = *(const float4*)(g_C1 + (size_t)w * 384 + 256 + lane * 4);
    float4 bl = *(const float4*)(bl0 + lane * 4);
    float4 bv = *(const float4*)(bp + lane * 4);
    float4 o;
    o.x = fmaxf(fmaf(a0, dinv, bl.x + r.x), 0.f) + pj.x + bv.x;
    o.y = fmaxf(fmaf(a1, dinv, bl.y + r.y), 0.f) + pj.y + bv.y;
    o.z = fmaxf(fmaf(a2, dinv, bl.z + r.z), 0.f) + pj.z + bv.z;
    o.w = fmaxf(fmaf(a3, dinv, bl.w + r.w), 0.f) + pj.w + bv.w;
    *(float4*)(g_h1 + (size_t)w * DH + lane * 4) = o;
    __nv_bfloat162 q0 = __floats2bfloat162_rn(o.x, o.y);
    __nv_bfloat162 q1 = __floats2bfloat162_rn(o.z, o.w);
    uint2 qo; qo.x = *reinterpret_cast<uint32_t*>(&q0); qo.y = *reinterpret_cast<uint32_t*>(&q1);
    *((uint2*)(g_h1b + (size_t)w * DH) + lane) = qo;
}

// ---------------- fused pull-aggregation + node epilogue, layer 1 ----------------
__global__ __launch_bounds__(256)
void agg1_kernel(const float* __restrict__ bl1, int N) {
    int w = (blockIdx.x * blockDim.x + threadIdx.x) >> 5;
    int lane = threadIdx.x & 31;
    if (w >= N) return;
    int nbeg = g_rowptr[w], nend = g_rowptr[w + 1];
    float a0 = 0.f, a1 = 0.f, a2 = 0.f, a3 = 0.f;
    int j = nbeg;
    for (; j + 4 <= nend; j += 4) {
        int s0 = g_csr_src[j], s1 = g_csr_src[j + 1], s2 = g_csr_src[j + 2], s3 = g_csr_src[j + 3];
        uint2 v0 = *((const uint2*)(g_msg2 + (size_t)s0 * DH) + lane);
        uint2 v1 = *((const uint2*)(g_msg2 + (size_t)s1 * DH) + lane);
        uint2 v2 = *((const uint2*)(g_msg2 + (size_t)s2 * DH) + lane);
        uint2 v3 = *((const uint2*)(g_msg2 + (size_t)s3 * DH) + lane);
        float2 p;
        p = __bfloat1622float2(*reinterpret_cast<__nv_bfloat162*>(&v0.x)); a0 += p.x; a1 += p.y;
        p = __bfloat1622float2(*reinterpret_cast<__nv_bfloat162*>(&v0.y)); a2 += p.x; a3 += p.y;
        p = __bfloat1622float2(*reinterpret_cast<__nv_bfloat162*>(&v1.x)); a0 += p.x; a1 += p.y;
        p = __bfloat1622float2(*reinterpret_cast<__nv_bfloat162*>(&v1.y)); a2 += p.x; a3 += p.y;
        p = __bfloat1622float2(*reinterpret_cast<__nv_bfloat162*>(&v2.x)); a0 += p.x; a1 += p.y;
        p = __bfloat1622float2(*reinterpret_cast<__nv_bfloat162*>(&v2.y)); a2 += p.x; a3 += p.y;
        p = __bfloat1622float2(*reinterpret_cast<__nv_bfloat162*>(&v3.x)); a0 += p.x; a1 += p.y;
        p = __bfloat1622float2(*reinterpret_cast<__nv_bfloat162*>(&v3.y)); a2 += p.x; a3 += p.y;
    }
    for (; j < nend; j++) {
        int s = g_csr_src[j];
        uint2 v = *((const uint2*)(g_msg2 + (size_t)s * DH) + lane);
        float2 p;
        p = __bfloat1622float2(*reinterpret_cast<__nv_bfloat162*>(&v.x)); a0 += p.x; a1 += p.y;
        p = __bfloat1622float2(*reinterpret_cast<__nv_bfloat162*>(&v.y)); a2 += p.x; a3 += p.y;
    }
    float dinv = 1.0f / fmaxf((float)(nend - nbeg), 1.0f);
    float4 r  = *(const float4*)(g_C2 + (size_t)w * 256 + 128 + lane * 4);
    float4 hp = *(const float4*)(g_h1 + (size_t)w * DH + lane * 4);
    float4 bl = *(const float4*)(bl1 + lane * 4);
    float4 o;
    o.x = fmaxf(fmaf(a0, dinv, bl.x + r.x), 0.f) + hp.x;
    o.y = fmaxf(fmaf(a1, dinv, bl.y + r.y), 0.f) + hp.y;
    o.z = fmaxf(fmaf(a2, dinv, bl.z + r.z), 0.f) + hp.z;
    o.w = fmaxf(fmaf(a3, dinv, bl.w + r.w), 0.f) + hp.w;
    *(float4*)(g_h2 + (size_t)w * DH + lane * 4) = o;
}

// ---------------- fused MLP head + blend ----------------
__global__ __launch_bounds__(256)
void head_kernel(const float* __restrict__ W1, const float* __restrict__ b1,
                 const float* __restrict__ W2, const float* __restrict__ b2,
                 const float* __restrict__ rer, const float* __restrict__ alogit,
                 float* __restrict__ out, int N) {
    __shared__ float W1s[128 * 64];
    __shared__ float b1s[64];
    __shared__ float W2s[64];

    for (int k = threadIdx.x; k < 128 * 64; k += blockDim.x) W1s[k] = W1[k];
    if (threadIdx.x < 64) { b1s[threadIdx.x] = b1[threadIdx.x]; W2s[threadIdx.x] = W2[threadIdx.x]; }
    __syncthreads();

    int i = blockIdx.x * blockDim.x + threadIdx.x;
    if (i >= N) return;

    float acc[64];
#pragma unroll
    for (int j = 0; j < 64; j++) acc[j] = b1s[j];

    const float4* h4 = (const float4*)(g_h2 + (size_t)i * DH);
#pragma unroll 4
    for (int k4 = 0; k4 < 32; k4++) {
        float4 xv = h4[k4];
        float xs[4] = {xv.x, xv.y, xv.z, xv.w};
#pragma unroll
        for (int kk = 0; kk < 4; kk++) {
            float xk = xs[kk];
            int k = k4 * 4 + kk;
            const float4* wrow = (const float4*)&W1s[k * 64];
#pragma unroll
            for (int j4 = 0; j4 < 16; j4++) {
                float4 w = wrow[j4];
                acc[j4 * 4 + 0] = fmaf(xk, w.x, acc[j4 * 4 + 0]);
                acc[j4 * 4 + 1] = fmaf(xk, w.y, acc[j4 * 4 + 1]);
                acc[j4 * 4 + 2] = fmaf(xk, w.z, acc[j4 * 4 + 2]);
                acc[j4 * 4 + 3] = fmaf(xk, w.w, acc[j4 * 4 + 3]);
            }
        }
    }

    float s = b2[0];
#pragma unroll
    for (int j = 0; j < 64; j++) s = fmaf(fmaxf(acc[j], 0.f), W2s[j], s);

    float alpha = 1.0f / (1.0f + __expf(-alogit[0]));
    out[i] = alpha * rer[i] + (1.0f - alpha) * s;
}

// ---------------- launch ----------------
extern "C" void kernel_launch(void* const* d_in, const int* in_sizes, int n_in,
                              void* d_out, int out_size) {
    const float* x     = (const float*)d_in[0];
    const int*   eidx  = (const int*)d_in[1];
    const float* rer   = (const float*)d_in[2];
    const float* Wp    = (const float*)d_in[3];
    const float* bp    = (const float*)d_in[4];
    const float* Wl0   = (const float*)d_in[5];
    const float* bl0   = (const float*)d_in[6];
    const float* Wr0   = (const float*)d_in[7];
    const float* Wl1   = (const float*)d_in[8];
    const float* bl1   = (const float*)d_in[9];
    const float* Wr1   = (const float*)d_in[10];
    const float* W1    = (const float*)d_in[11];
    const float* b1    = (const float*)d_in[12];
    const float* W2    = (const float*)d_in[13];
    const float* b2    = (const float*)d_in[14];
    const float* alog  = (const float*)d_in[15];
    float* out = (float*)d_out;

    const int N = in_sizes[0] / DIN;       // 50000
    const int E = in_sizes[1] / 2;         // 800000
    const int* src = eidx;
    const int* dst = eidx + E;

    float *C1, *C2;
    __nv_bfloat16 *xb, *h1b, *msg1, *msg2;
    uint32_t *Bp1b, *Bp2b;
    cudaGetSymbolAddress((void**)&C1,   g_C1);
    cudaGetSymbolAddress((void**)&C2,   g_C2);
    cudaGetSymbolAddress((void**)&xb,   g_xb);
    cudaGetSymbolAddress((void**)&h1b,  g_h1b);
    cudaGetSymbolAddress((void**)&msg1, g_msg1);
    cudaGetSymbolAddress((void**)&msg2, g_msg2);
    cudaGetSymbolAddress((void**)&Bp1b, g_Bp1b);
    cudaGetSymbolAddress((void**)&Bp2b, g_Bp2b);

    // pack weights (bf16 pairs) + zero deg
    {
        int nthr = (DIN / 2) * 384;
        int grid = (max(nthr, N) + 255) / 256;
        pack_kernel<<<grid, 256>>>(Wl0, Wr0, Wp, Wl1, Wr1);
    }

    // x -> bf16 + degree histogram (merged)
    {
        int nWords = N * DIN / 2;
        prep_kernel<<<(nWords + 255) / 256, 256>>>(x, dst, nWords, E);
    }

    // multi-block exclusive scan -> rowptr, cursor
    int nb = (N + 1023) / 1024;
    scan_blocks<<<nb, 1024>>>(N);
    scan_tops<<<1, 64>>>(nb, N);
    scan_add<<<(N + 255) / 256, 256>>>(N);

    // CSR fill
    csr_fill<<<(E + 255) / 256, 256>>>(src, dst, E);

    // GEMM1: xb[N,256] @ Bp1b -> msg1 (bf16, block 0) + C1 (fp32, blocks 1,2)
    {
        dim3 grid(384 / 128, (N + 127) / 128);
        gemm_bf16<<<grid, 256>>>(xb, Bp1b, C1, msg1, N, DIN, 384);
    }

    // pull-agg layer 0 + epilogue -> h1 (fp32 + bf16)
    agg0_kernel<<<(N * 32 + 255) / 256, 256>>>(bl0, bp, N);

    // GEMM2: h1b[N,128] @ Bp2b -> msg2 (bf16, block 0) + C2 (fp32, block 1)
    {
        dim3 grid(256 / 128, (N + 127) / 128);
        gemm_bf16<<<grid, 256>>>(h1b, Bp2b, C2, msg2, N, DH, 256);
    }

    // pull-agg layer 1 + epilogue -> h2
    agg1_kernel<<<(N * 32 + 255) / 256, 256>>>(bl1, N);

    // MLP head + blend
    head_kernel<<<(N + 255) / 256, 256>>>(W1, b1, W2, b2, rer, alog, out, N);
}

// round 6
// speedup vs baseline: 2.9895x; 1.1818x over previous
#include <cuda_runtime.h>
#include <cuda_bf16.h>
#include <math.h>
#include <stdint.h>

#define NN   50000
#define EE   800000
#define DIN  256
#define DH   128

// ---------------- scratch (static device globals; no allocation) ----------------
__device__ __align__(16) __nv_bfloat16 g_C1b[(size_t)NN * 384];   // bf16: msg | r0 | proj
__device__ __align__(16) __nv_bfloat16 g_C2b[(size_t)NN * 256];   // bf16: msg | r1
__device__ __align__(16) float g_h1[(size_t)NN * DH];
__device__ __align__(16) __nv_bfloat16 g_xb [(size_t)NN * DIN];   // x in bf16
__device__ __align__(16) __nv_bfloat16 g_h1b[(size_t)NN * DH];    // h1 in bf16
__device__ __align__(16) __nv_bfloat16 g_h2b[(size_t)NN * DH];    // h2 in bf16
__device__ int g_deg[NN];
__device__ int g_rowptr[NN + 1];
__device__ int g_cursor[NN];
__device__ int g_csr_src[EE];
__device__ int g_bsum[64];
__device__ int g_boff[64];
__device__ __align__(16) uint32_t g_Bp1b[(DIN / 2) * 384];        // bf16 pairs [kpair][384]
__device__ __align__(16) uint32_t g_Bp2b[(DH / 2) * 256];         // bf16 pairs [kpair][256]

// ---------------- pack weights to bf16 k-pair layout + zero deg ----------------
__global__ void pack_kernel(const float* __restrict__ Wl0, const float* __restrict__ Wr0,
                            const float* __restrict__ Wp,
                            const float* __restrict__ Wl1, const float* __restrict__ Wr1) {
    int idx = blockIdx.x * blockDim.x + threadIdx.x;
    if (idx < (DIN / 2) * 384) {
        int kp = idx / 384, j = idx % 384;
        int k0 = 2 * kp, k1 = 2 * kp + 1;
        float lo, hi;
        if (j < 128)      { lo = Wl0[k0 * DH + j];        hi = Wl0[k1 * DH + j]; }
        else if (j < 256) { lo = Wr0[k0 * DH + j - 128];  hi = Wr0[k1 * DH + j - 128]; }
        else              { lo = Wp [k0 * DH + j - 256];  hi = Wp [k1 * DH + j - 256]; }
        __nv_bfloat162 p = __floats2bfloat162_rn(lo, hi);
        g_Bp1b[idx] = *reinterpret_cast<uint32_t*>(&p);
    }
    if (idx < (DH / 2) * 256) {
        int kp = idx / 256, j = idx % 256;
        int k0 = 2 * kp, k1 = 2 * kp + 1;
        float lo, hi;
        if (j < 128) { lo = Wl1[k0 * DH + j];       hi = Wl1[k1 * DH + j]; }
        else         { lo = Wr1[k0 * DH + j - 128]; hi = Wr1[k1 * DH + j - 128]; }
        __nv_bfloat162 p = __floats2bfloat162_rn(lo, hi);
        g_Bp2b[idx] = *reinterpret_cast<uint32_t*>(&p);
    }
    if (idx < NN) g_deg[idx] = 0;
}

// ---------------- x -> bf16  +  degree histogram (merged) ----------------
__global__ void prep_kernel(const float* __restrict__ x, const int* __restrict__ dst,
                            int nWords, int E) {
    int i = blockIdx.x * blockDim.x + threadIdx.x;
    if (i < nWords) {
        float2 v = ((const float2*)x)[i];
        __nv_bfloat162 p = __floats2bfloat162_rn(v.x, v.y);
        ((uint32_t*)g_xb)[i] = *reinterpret_cast<uint32_t*>(&p);
    }
    if (i < E) atomicAdd(&g_deg[dst[i]], 1);
}

// ---------------- multi-block exclusive scan ----------------
__global__ __launch_bounds__(1024)
void scan_blocks(int N) {
    __shared__ int wsum[32];
    int lane = threadIdx.x & 31, wid = threadIdx.x >> 5;
    int idx = blockIdx.x * 1024 + threadIdx.x;
    int v = (idx < N) ? g_deg[idx] : 0;
    int x = v;
#pragma unroll
    for (int o = 1; o < 32; o <<= 1) {
        int y = __shfl_up_sync(0xffffffffu, x, o);
        if (lane >= o) x += y;
    }
    if (lane == 31) wsum[wid] = x;
    __syncthreads();
    if (wid == 0) {
        int s = wsum[lane];
#pragma unroll
        for (int o = 1; o < 32; o <<= 1) {
            int y = __shfl_up_sync(0xffffffffu, s, o);
            if (lane >= o) s += y;
        }
        wsum[lane] = s;
    }
    __syncthreads();
    int excl = x - v + (wid > 0 ? wsum[wid - 1] : 0);
    if (idx < N) g_rowptr[idx] = excl;
    if (threadIdx.x == 1023) g_bsum[blockIdx.x] = excl + v;
}

__global__ __launch_bounds__(64)
void scan_tops(int nb, int N) {
    __shared__ int wsum[2];
    int t = threadIdx.x;
    int lane = t & 31, wid = t >> 5;
    int v = (t < nb) ? g_bsum[t] : 0;
    int x = v;
#pragma unroll
    for (int o = 1; o < 32; o <<= 1) {
        int y = __shfl_up_sync(0xffffffffu, x, o);
        if (lane >= o) x += y;
    }
    if (lane == 31) wsum[wid] = x;
    __syncthreads();
    int excl = x - v + (wid > 0 ? wsum[0] : 0);
    if (t < nb) g_boff[t] = excl;
    if (t == nb - 1) g_rowptr[N] = excl + v;
}

__global__ void scan_add(int N) {
    int i = blockIdx.x * blockDim.x + threadIdx.x;
    if (i >= N) return;
    int r = g_rowptr[i] + g_boff[i >> 10];
    g_rowptr[i] = r;
    g_cursor[i] = r;
}

__global__ void csr_fill(const int* __restrict__ src, const int* __restrict__ dst, int E) {
    int e = blockIdx.x * blockDim.x + threadIdx.x;
    if (e >= E) return;
    int slot = atomicAdd(&g_cursor[dst[e]], 1);
    g_csr_src[slot] = src[e];
}

// ---------------- bf16 tensor-core GEMM (m16n8k16), bf16 output ----------------
#define SPAD 136

__device__ __forceinline__ void mma_bf16(float c[4], uint32_t a0, uint32_t a1,
                                         uint32_t a2, uint32_t a3,
                                         uint32_t b0, uint32_t b1) {
    asm volatile(
        "mma.sync.aligned.m16n8k16.row.col.f32.bf16.bf16.f32 "
        "{%0,%1,%2,%3}, {%4,%5,%6,%7}, {%8,%9}, {%0,%1,%2,%3};"
        : "+f"(c[0]), "+f"(c[1]), "+f"(c[2]), "+f"(c[3])
        : "r"(a0), "r"(a1), "r"(a2), "r"(a3), "r"(b0), "r"(b1));
}

__global__ __launch_bounds__(256)
void gemm_bf16(const __nv_bfloat16* __restrict__ A, const uint32_t* __restrict__ Bp,
               __nv_bfloat16* __restrict__ Cb, int M, int K, int Ncol) {
    __shared__ uint32_t As[16][SPAD];   // [kpair][m]
    __shared__ uint32_t Bs[16][SPAD];   // [kpair][n]

    const int t = threadIdx.x;
    const int lane = t & 31;
    const int warp = t >> 5;
    const int wm = (warp & 1) * 64;
    const int wn = (warp >> 1) * 32;
    const int g = lane >> 2;
    const int t4 = lane & 3;

    const int rowBase = blockIdx.y * 128;
    const int colBase = blockIdx.x * 128;

    const int ar = t & 127;
    const int ah = t >> 7;
    const int bkp = t >> 4;
    const int bcol = (t & 15) * 8;

    float acc[4][4][4];
#pragma unroll
    for (int mt = 0; mt < 4; mt++)
#pragma unroll
        for (int nt = 0; nt < 4; nt++)
#pragma unroll
            for (int i = 0; i < 4; i++) acc[mt][nt][i] = 0.f;

    const int grow = rowBase + ar;
    const bool arow_ok = (grow < M);
    const __nv_bfloat16* aBase = A + (size_t)grow * K + ah * 16;
    const uint32_t* bBase = Bp + (size_t)bkp * Ncol + colBase + bcol;

    uint4 ra0, ra1, rb0, rb1;

    if (arow_ok) {
        ra0 = *(const uint4*)(aBase);
        ra1 = *(const uint4*)(aBase + 8);
    } else {
        ra0 = make_uint4(0, 0, 0, 0); ra1 = make_uint4(0, 0, 0, 0);
    }
    rb0 = *(const uint4*)(bBase);
    rb1 = *(const uint4*)(bBase + 4);

    const int nChunks = K >> 5;
    for (int ci = 0; ci < nChunks; ci++) {
        {
            const int kb = ah * 8;
            As[kb + 0][ar] = ra0.x; As[kb + 1][ar] = ra0.y;
            As[kb + 2][ar] = ra0.z; As[kb + 3][ar] = ra0.w;
            As[kb + 4][ar] = ra1.x; As[kb + 5][ar] = ra1.y;
            As[kb + 6][ar] = ra1.z; As[kb + 7][ar] = ra1.w;
            *(uint4*)&Bs[bkp][bcol]     = rb0;
            *(uint4*)&Bs[bkp][bcol + 4] = rb1;
        }
        __syncthreads();

        if (ci + 1 < nChunks) {
            int k0 = (ci + 1) << 5;
            if (arow_ok) {
                ra0 = *(const uint4*)(aBase + k0);
                ra1 = *(const uint4*)(aBase + k0 + 8);
            }
            rb0 = *(const uint4*)(bBase + (size_t)(k0 >> 1) * Ncol);
            rb1 = *(const uint4*)(bBase + (size_t)(k0 >> 1) * Ncol + 4);
        }

#pragma unroll
        for (int kk = 0; kk < 2; kk++) {
            const int kb = kk * 8;
            uint32_t af[4][4];
#pragma unroll
            for (int mt = 0; mt < 4; mt++) {
                int r = wm + mt * 16 + g;
                af[mt][0] = As[kb + t4][r];
                af[mt][1] = As[kb + t4][r + 8];
                af[mt][2] = As[kb + t4 + 4][r];
                af[mt][3] = As[kb + t4 + 4][r + 8];
            }
#pragma unroll
            for (int nt = 0; nt < 4; nt++) {
                int cn = wn + nt * 8 + g;
                uint32_t b0 = Bs[kb + t4][cn];
                uint32_t b1 = Bs[kb + t4 + 4][cn];
#pragma unroll
                for (int mt = 0; mt < 4; mt++)
                    mma_bf16(acc[mt][nt], af[mt][0], af[mt][1], af[mt][2], af[mt][3], b0, b1);
            }
        }
        __syncthreads();
    }

    // epilogue: bf16 pairs
#pragma unroll
    for (int mt = 0; mt < 4; mt++) {
        int r0 = rowBase + wm + mt * 16 + g;
#pragma unroll
        for (int nt = 0; nt < 4; nt++) {
            int col = colBase + wn + nt * 8 + 2 * t4;
            if (r0 < M)
                *(__nv_bfloat162*)(Cb + (size_t)r0 * Ncol + col) =
                    __floats2bfloat162_rn(acc[mt][nt][0], acc[mt][nt][1]);
            if (r0 + 8 < M)
                *(__nv_bfloat162*)(Cb + (size_t)(r0 + 8) * Ncol + col) =
                    __floats2bfloat162_rn(acc[mt][nt][2], acc[mt][nt][3]);
        }
    }
}

// ---------------- bf16x4 -> 4 floats helper ----------------
__device__ __forceinline__ void bf4(uint2 u, float& f0, float& f1, float& f2, float& f3) {
    float2 p0 = __bfloat1622float2(*reinterpret_cast<__nv_bfloat162*>(&u.x));
    float2 p1 = __bfloat1622float2(*reinterpret_cast<__nv_bfloat162*>(&u.y));
    f0 = p0.x; f1 = p0.y; f2 = p1.x; f3 = p1.y;
}

// ---------------- fused pull-aggregation + node epilogue, layer 0 ----------------
// msg rows = g_C1b cols 0:128 (row stride 384)
__global__ __launch_bounds__(256)
void agg0_kernel(const float* __restrict__ bl0, const float* __restrict__ bp, int N) {
    int w = (blockIdx.x * blockDim.x + threadIdx.x) >> 5;
    int lane = threadIdx.x & 31;
    if (w >= N) return;
    int nbeg = g_rowptr[w], nend = g_rowptr[w + 1];
    float a0 = 0.f, a1 = 0.f, a2 = 0.f, a3 = 0.f;
    int j = nbeg;
    for (; j + 4 <= nend; j += 4) {
        int s0 = g_csr_src[j], s1 = g_csr_src[j + 1], s2 = g_csr_src[j + 2], s3 = g_csr_src[j + 3];
        uint2 v0 = *((const uint2*)(g_C1b + (size_t)s0 * 384) + lane);
        uint2 v1 = *((const uint2*)(g_C1b + (size_t)s1 * 384) + lane);
        uint2 v2 = *((const uint2*)(g_C1b + (size_t)s2 * 384) + lane);
        uint2 v3 = *((const uint2*)(g_C1b + (size_t)s3 * 384) + lane);
        float f0, f1, f2, f3;
        bf4(v0, f0, f1, f2, f3); a0 += f0; a1 += f1; a2 += f2; a3 += f3;
        bf4(v1, f0, f1, f2, f3); a0 += f0; a1 += f1; a2 += f2; a3 += f3;
        bf4(v2, f0, f1, f2, f3); a0 += f0; a1 += f1; a2 += f2; a3 += f3;
        bf4(v3, f0, f1, f2, f3); a0 += f0; a1 += f1; a2 += f2; a3 += f3;
    }
    for (; j < nend; j++) {
        int s = g_csr_src[j];
        uint2 v = *((const uint2*)(g_C1b + (size_t)s * 384) + lane);
        float f0, f1, f2, f3;
        bf4(v, f0, f1, f2, f3); a0 += f0; a1 += f1; a2 += f2; a3 += f3;
    }
    float dinv = 1.0f / fmaxf((float)(nend - nbeg), 1.0f);
    float r0, r1, r2, r3, p0, p1, p2, p3;
    bf4(*(const uint2*)(g_C1b + (size_t)w * 384 + 128 + lane * 4), r0, r1, r2, r3);
    bf4(*(const uint2*)(g_C1b + (size_t)w * 384 + 256 + lane * 4), p0, p1, p2, p3);
    float4 bl = *(const float4*)(bl0 + lane * 4);
    float4 bv = *(const float4*)(bp + lane * 4);
    float4 o;
    o.x = fmaxf(fmaf(a0, dinv, bl.x + r0), 0.f) + p0 + bv.x;
    o.y = fmaxf(fmaf(a1, dinv, bl.y + r1), 0.f) + p1 + bv.y;
    o.z = fmaxf(fmaf(a2, dinv, bl.z + r2), 0.f) + p2 + bv.z;
    o.w = fmaxf(fmaf(a3, dinv, bl.w + r3), 0.f) + p3 + bv.w;
    *(float4*)(g_h1 + (size_t)w * DH + lane * 4) = o;
    __nv_bfloat162 q0 = __floats2bfloat162_rn(o.x, o.y);
    __nv_bfloat162 q1 = __floats2bfloat162_rn(o.z, o.w);
    uint2 qo; qo.x = *reinterpret_cast<uint32_t*>(&q0); qo.y = *reinterpret_cast<uint32_t*>(&q1);
    *((uint2*)(g_h1b + (size_t)w * DH) + lane) = qo;
}

// ---------------- fused pull-aggregation + node epilogue, layer 1 ----------------
// msg rows = g_C2b cols 0:128 (row stride 256); writes h2 bf16 only
__global__ __launch_bounds__(256)
void agg1_kernel(const float* __restrict__ bl1, int N) {
    int w = (blockIdx.x * blockDim.x + threadIdx.x) >> 5;
    int lane = threadIdx.x & 31;
    if (w >= N) return;
    int nbeg = g_rowptr[w], nend = g_rowptr[w + 1];
    float a0 = 0.f, a1 = 0.f, a2 = 0.f, a3 = 0.f;
    int j = nbeg;
    for (; j + 4 <= nend; j += 4) {
        int s0 = g_csr_src[j], s1 = g_csr_src[j + 1], s2 = g_csr_src[j + 2], s3 = g_csr_src[j + 3];
        uint2 v0 = *((const uint2*)(g_C2b + (size_t)s0 * 256) + lane);
        uint2 v1 = *((const uint2*)(g_C2b + (size_t)s1 * 256) + lane);
        uint2 v2 = *((const uint2*)(g_C2b + (size_t)s2 * 256) + lane);
        uint2 v3 = *((const uint2*)(g_C2b + (size_t)s3 * 256) + lane);
        float f0, f1, f2, f3;
        bf4(v0, f0, f1, f2, f3); a0 += f0; a1 += f1; a2 += f2; a3 += f3;
        bf4(v1, f0, f1, f2, f3); a0 += f0; a1 += f1; a2 += f2; a3 += f3;
        bf4(v2, f0, f1, f2, f3); a0 += f0; a1 += f1; a2 += f2; a3 += f3;
        bf4(v3, f0, f1, f2, f3); a0 += f0; a1 += f1; a2 += f2; a3 += f3;
    }
    for (; j < nend; j++) {
        int s = g_csr_src[j];
        uint2 v = *((const uint2*)(g_C2b + (size_t)s * 256) + lane);
        float f0, f1, f2, f3;
        bf4(v, f0, f1, f2, f3); a0 += f0; a1 += f1; a2 += f2; a3 += f3;
    }
    float dinv = 1.0f / fmaxf((float)(nend - nbeg), 1.0f);
    float r0, r1, r2, r3;
    bf4(*(const uint2*)(g_C2b + (size_t)w * 256 + 128 + lane * 4), r0, r1, r2, r3);
    float4 hp = *(const float4*)(g_h1 + (size_t)w * DH + lane * 4);
    float4 bl = *(const float4*)(bl1 + lane * 4);
    float o0 = fmaxf(fmaf(a0, dinv, bl.x + r0), 0.f) + hp.x;
    float o1 = fmaxf(fmaf(a1, dinv, bl.y + r1), 0.f) + hp.y;
    float o2 = fmaxf(fmaf(a2, dinv, bl.z + r2), 0.f) + hp.z;
    float o3 = fmaxf(fmaf(a3, dinv, bl.w + r3), 0.f) + hp.w;
    __nv_bfloat162 q0 = __floats2bfloat162_rn(o0, o1);
    __nv_bfloat162 q1 = __floats2bfloat162_rn(o2, o3);
    uint2 qo; qo.x = *reinterpret_cast<uint32_t*>(&q0); qo.y = *reinterpret_cast<uint32_t*>(&q1);
    *((uint2*)(g_h2b + (size_t)w * DH) + lane) = qo;
}

// ---------------- MMA head: gnn = relu(h2b@W1 + b1)@W2 + b2; blend ----------------
// 128 rows/block, 8 warps = 2(M) x 4(N16). K=128 (8 k16 steps). Dynamic smem:
//   region0: As[64 kp][136]  (8704 w)  -> reused as Cs[128][72] (9216 w)
//   region1: Bs[64 kp][72]   (4608 w)
__global__ __launch_bounds__(256)
void head_mma(const float* __restrict__ W1, const float* __restrict__ b1,
              const float* __restrict__ W2, const float* __restrict__ b2,
              const float* __restrict__ rer, const float* __restrict__ alogit,
              float* __restrict__ out, int N) {
    extern __shared__ uint32_t sm[];
    uint32_t* As = sm;               // 9216 words region (As uses 8704)
    uint32_t* Bs = sm + 9216;        // 4608 words
    float* Cs = (float*)sm;          // aliases As region after compute
    __shared__ float b1s[64];
    __shared__ float W2s[64];

    const int t = threadIdx.x;
    const int lane = t & 31;
    const int warp = t >> 5;
    const int wm = (warp & 1) * 64;
    const int wn = (warp >> 1) * 16;
    const int g = lane >> 2;
    const int t4 = lane & 3;
    const int rowBase = blockIdx.x * 128;

    // stage B: W1 fp32 [128][64] -> bf16 pairs Bs[kp][col]
    for (int idx = t; idx < 64 * 64; idx += 256) {
        int kp = idx >> 6, col = idx & 63;
        __nv_bfloat162 p = __floats2bfloat162_rn(W1[(2 * kp) * 64 + col],
                                                 W1[(2 * kp + 1) * 64 + col]);
        Bs[kp * 72 + col] = *reinterpret_cast<uint32_t*>(&p);
    }
    if (t < 64) { b1s[t] = b1[t]; W2s[t] = W2[t]; }

    // stage A: h2b rows -> As[kp][row]
    {
        int row = t & 127;
        int half = t >> 7;
        bool ok = (rowBase + row) < N;
        const uint4* aRow = (const uint4*)(g_h2b + (size_t)(rowBase + row) * DH);
#pragma unroll
        for (int q = 0; q < 8; q++) {
            uint4 u = ok ? aRow[half * 8 + q] : make_uint4(0, 0, 0, 0);
            int kp = (half * 8 + q) * 4;
            As[(kp + 0) * SPAD + row] = u.x;
            As[(kp + 1) * SPAD + row] = u.y;
            As[(kp + 2) * SPAD + row] = u.z;
            As[(kp + 3) * SPAD + row] = u.w;
        }
    }
    __syncthreads();

    float acc[4][2][4];
#pragma unroll
    for (int mt = 0; mt < 4; mt++)
#pragma unroll
        for (int nt = 0; nt < 2; nt++)
#pragma unroll
            for (int i = 0; i < 4; i++) acc[mt][nt][i] = 0.f;

#pragma unroll
    for (int step = 0; step < 8; step++) {
        const int kb = step * 8;
        uint32_t af[4][4];
#pragma unroll
        for (int mt = 0; mt < 4; mt++) {
            int r = wm + mt * 16 + g;
            af[mt][0] = As[(kb + t4) * SPAD + r];
            af[mt][1] = As[(kb + t4) * SPAD + r + 8];
            af[mt][2] = As[(kb + t4 + 4) * SPAD + r];
            af[mt][3] = As[(kb + t4 + 4) * SPAD + r + 8];
        }
#pragma unroll
        for (int nt = 0; nt < 2; nt++) {
            int cn = wn + nt * 8 + g;
            uint32_t b0 = Bs[(kb + t4) * 72 + cn];
            uint32_t b1r = Bs[(kb + t4 + 4) * 72 + cn];
#pragma unroll
            for (int mt = 0; mt < 4; mt++)
                mma_bf16(acc[mt][nt], af[mt][0], af[mt][1], af[mt][2], af[mt][3], b0, b1r);
        }
    }
    __syncthreads();   // all As reads done before aliasing as Cs

    // write acc to Cs[128][72]
#pragma unroll
    for (int mt = 0; mt < 4; mt++) {
        int r = wm + mt * 16 + g;
#pragma unroll
        for (int nt = 0; nt < 2; nt++) {
            int col = wn + nt * 8 + 2 * t4;
            Cs[r * 72 + col]       = acc[mt][nt][0];
            Cs[r * 72 + col + 1]   = acc[mt][nt][1];
            Cs[(r + 8) * 72 + col]     = acc[mt][nt][2];
            Cs[(r + 8) * 72 + col + 1] = acc[mt][nt][3];
        }
    }
    __syncthreads();

    // reduce: 2 threads per row, 32 cols each
    {
        int row = t >> 1;
        int hc = (t & 1) * 32;
        float s = 0.f;
#pragma unroll
        for (int c = 0; c < 32; c++) {
            int col = hc + c;
            s = fmaf(fmaxf(Cs[row * 72 + col] + b1s[col], 0.f), W2s[col], s);
        }
        s += __shfl_xor_sync(0xffffffffu, s, 1);
        int gr = rowBase + row;
        if ((t & 1) == 0 && gr < N) {
            float gnn = s + b2[0];
            float alpha = 1.0f / (1.0f + __expf(-alogit[0]));
            out[gr] = alpha * rer[gr] + (1.0f - alpha) * gnn;
        }
    }
}

// ---------------- launch ----------------
extern "C" void kernel_launch(void* const* d_in, const int* in_sizes, int n_in,
                              void* d_out, int out_size) {
    const float* x     = (const float*)d_in[0];
    const int*   eidx  = (const int*)d_in[1];
    const float* rer   = (const float*)d_in[2];
    const float* Wp    = (const float*)d_in[3];
    const float* bp    = (const float*)d_in[4];
    const float* Wl0   = (const float*)d_in[5];
    const float* bl0   = (const float*)d_in[6];
    const float* Wr0   = (const float*)d_in[7];
    const float* Wl1   = (const float*)d_in[8];
    const float* bl1   = (const float*)d_in[9];
    const float* Wr1   = (const float*)d_in[10];
    const float* W1    = (const float*)d_in[11];
    const float* b1    = (const float*)d_in[12];
    const float* W2    = (const float*)d_in[13];
    const float* b2    = (const float*)d_in[14];
    const float* alog  = (const float*)d_in[15];
    float* out = (float*)d_out;

    const int N = in_sizes[0] / DIN;       // 50000
    const int E = in_sizes[1] / 2;         // 800000
    const int* src = eidx;
    const int* dst = eidx + E;

    __nv_bfloat16 *C1b, *C2b, *xb, *h1b;
    uint32_t *Bp1b, *Bp2b;
    cudaGetSymbolAddress((void**)&C1b,  g_C1b);
    cudaGetSymbolAddress((void**)&C2b,  g_C2b);
    cudaGetSymbolAddress((void**)&xb,   g_xb);
    cudaGetSymbolAddress((void**)&h1b,  g_h1b);
    cudaGetSymbolAddress((void**)&Bp1b, g_Bp1b);
    cudaGetSymbolAddress((void**)&Bp2b, g_Bp2b);

    // head_mma dynamic smem: (9216 + 4608) * 4 = 55296 B > 48K default
    static int smem_set = 0;
    if (!smem_set) {
        cudaFuncSetAttribute(head_mma, cudaFuncAttributeMaxDynamicSharedMemorySize, 55296);
        smem_set = 1;
    }

    // pack weights (bf16 pairs) + zero deg
    {
        int nthr = (DIN / 2) * 384;
        int grid = (max(nthr, N) + 255) / 256;
        pack_kernel<<<grid, 256>>>(Wl0, Wr0, Wp, Wl1, Wr1);
    }

    // x -> bf16 + degree histogram
    {
        int nWords = N * DIN / 2;
        prep_kernel<<<(nWords + 255) / 256, 256>>>(x, dst, nWords, E);
    }

    // multi-block exclusive scan -> rowptr, cursor
    int nb = (N + 1023) / 1024;
    scan_blocks<<<nb, 1024>>>(N);
    scan_tops<<<1, 64>>>(nb, N);
    scan_add<<<(N + 255) / 256, 256>>>(N);

    // CSR fill
    csr_fill<<<(E + 255) / 256, 256>>>(src, dst, E);

    // GEMM1: xb[N,256] @ Bp1b -> C1b bf16 [N,384] (msg | r0 | proj)
    {
        dim3 grid(384 / 128, (N + 127) / 128);
        gemm_bf16<<<grid, 256>>>(xb, Bp1b, C1b, N, DIN, 384);
    }

    // pull-agg layer 0 + epilogue -> h1 fp32 + h1 bf16
    agg0_kernel<<<(N * 32 + 255) / 256, 256>>>(bl0, bp, N);

    // GEMM2: h1b[N,128] @ Bp2b -> C2b bf16 [N,256] (msg | r1)
    {
        dim3 grid(256 / 128, (N + 127) / 128);
        gemm_bf16<<<grid, 256>>>(h1b, Bp2b, C2b, N, DH, 256);
    }

    // pull-agg layer 1 + epilogue -> h2 bf16
    agg1_kernel<<<(N * 32 + 255) / 256, 256>>>(bl1, N);

    // MMA head + blend
    head_mma<<<(N + 127) / 128, 256, 55296>>>(W1, b1, W2, b2, rer, alog, out, N);
}

// round 7
// speedup vs baseline: 3.1319x; 1.0476x over previous
#include <cuda_runtime.h>
#include <cuda_bf16.h>
#include <math.h>
#include <stdint.h>

#define NN   50000
#define EE   800000
#define DIN  256
#define DH   128

// ---------------- scratch (static device globals; no allocation) ----------------
__device__ __align__(16) __nv_bfloat16 g_C1b[(size_t)NN * 384];   // bf16: msg | r0 | proj
__device__ __align__(16) __nv_bfloat16 g_C2b[(size_t)NN * 256];   // bf16: msg | r1
__device__ __align__(16) __nv_bfloat16 g_xb [(size_t)NN * DIN];   // x in bf16
__device__ __align__(16) __nv_bfloat16 g_h1b[(size_t)NN * DH];    // h1 in bf16
__device__ __align__(16) __nv_bfloat16 g_h2b[(size_t)NN * DH];    // h2 in bf16
__device__ int g_deg[NN];
__device__ int g_rowptr[NN + 1];
__device__ int g_cursor[NN];
__device__ int g_csr_src[EE];
__device__ int g_bsum[64];
__device__ __align__(16) uint32_t g_Bp1b[(DIN / 2) * 384];        // bf16 pairs [kpair][384]
__device__ __align__(16) uint32_t g_Bp2b[(DH / 2) * 256];         // bf16 pairs [kpair][256]

// ---------------- side-stream resources (created once, before any checkpoint) ---
static cudaStream_t g_s2 = nullptr;
static cudaEvent_t  g_evFork = nullptr, g_evJoin = nullptr;
namespace {
struct InitRes {
    InitRes() {
        cudaStreamCreateWithFlags(&g_s2, cudaStreamNonBlocking);
        cudaEventCreateWithFlags(&g_evFork, cudaEventDisableTiming);
        cudaEventCreateWithFlags(&g_evJoin, cudaEventDisableTiming);
    }
};
static InitRes g_initres;
}

// ---------------- pack weights to bf16 k-pair layout ----------------
__global__ void pack_kernel(const float* __restrict__ Wl0, const float* __restrict__ Wr0,
                            const float* __restrict__ Wp,
                            const float* __restrict__ Wl1, const float* __restrict__ Wr1) {
    int idx = blockIdx.x * blockDim.x + threadIdx.x;
    if (idx < (DIN / 2) * 384) {
        int kp = idx / 384, j = idx % 384;
        int k0 = 2 * kp, k1 = 2 * kp + 1;
        float lo, hi;
        if (j < 128)      { lo = Wl0[k0 * DH + j];        hi = Wl0[k1 * DH + j]; }
        else if (j < 256) { lo = Wr0[k0 * DH + j - 128];  hi = Wr0[k1 * DH + j - 128]; }
        else              { lo = Wp [k0 * DH + j - 256];  hi = Wp [k1 * DH + j - 256]; }
        __nv_bfloat162 p = __floats2bfloat162_rn(lo, hi);
        g_Bp1b[idx] = *reinterpret_cast<uint32_t*>(&p);
    }
    if (idx < (DH / 2) * 256) {
        int kp = idx / 256, j = idx % 256;
        int k0 = 2 * kp, k1 = 2 * kp + 1;
        float lo, hi;
        if (j < 128) { lo = Wl1[k0 * DH + j];       hi = Wl1[k1 * DH + j]; }
        else         { lo = Wr1[k0 * DH + j - 128]; hi = Wr1[k1 * DH + j - 128]; }
        __nv_bfloat162 p = __floats2bfloat162_rn(lo, hi);
        g_Bp2b[idx] = *reinterpret_cast<uint32_t*>(&p);
    }
}

// ---------------- x -> bf16 ----------------
__global__ void convert_x(const float* __restrict__ x, int nWords) {
    int i = blockIdx.x * blockDim.x + threadIdx.x;
    if (i >= nWords) return;
    float2 v = ((const float2*)x)[i];
    __nv_bfloat162 p = __floats2bfloat162_rn(v.x, v.y);
    ((uint32_t*)g_xb)[i] = *reinterpret_cast<uint32_t*>(&p);
}

// ---------------- CSR build chain (side stream) ----------------
__global__ void zero_deg(int N) {
    int i = blockIdx.x * blockDim.x + threadIdx.x;
    if (i < N) g_deg[i] = 0;
}

__global__ void hist_kernel(const int* __restrict__ dst, int E) {
    int e = blockIdx.x * blockDim.x + threadIdx.x;
    if (e < E) atomicAdd(&g_deg[dst[e]], 1);
}

__global__ __launch_bounds__(1024)
void scan_blocks(int N) {
    __shared__ int wsum[32];
    int lane = threadIdx.x & 31, wid = threadIdx.x >> 5;
    int idx = blockIdx.x * 1024 + threadIdx.x;
    int v = (idx < N) ? g_deg[idx] : 0;
    int x = v;
#pragma unroll
    for (int o = 1; o < 32; o <<= 1) {
        int y = __shfl_up_sync(0xffffffffu, x, o);
        if (lane >= o) x += y;
    }
    if (lane == 31) wsum[wid] = x;
    __syncthreads();
    if (wid == 0) {
        int s = wsum[lane];
#pragma unroll
        for (int o = 1; o < 32; o <<= 1) {
            int y = __shfl_up_sync(0xffffffffu, s, o);
            if (lane >= o) s += y;
        }
        wsum[lane] = s;
    }
    __syncthreads();
    int excl = x - v + (wid > 0 ? wsum[wid - 1] : 0);
    if (idx < N) g_rowptr[idx] = excl;
    if (threadIdx.x == 1023) g_bsum[blockIdx.x] = excl + v;
}

// fused top-scan + add: group offset computed per block by warp 0
__global__ void scan_add_fused(int N) {
    __shared__ int pre_s;
    int grp = blockIdx.x >> 2;   // blockDim 256, 4 blocks per 1024-group
    if (threadIdx.x < 32) {
        int s = 0;
        for (int g = threadIdx.x; g < grp; g += 32) s += g_bsum[g];
#pragma unroll
        for (int o = 16; o; o >>= 1) s += __shfl_xor_sync(0xffffffffu, s, o);
        if (threadIdx.x == 0) pre_s = s;
    }
    __syncthreads();
    int i = blockIdx.x * 256 + threadIdx.x;
    if (i < N) {
        int r = g_rowptr[i] + pre_s;
        g_rowptr[i] = r;
        g_cursor[i] = r;
        if (i == N - 1) g_rowptr[N] = r + g_deg[N - 1];
    }
}

__global__ void csr_fill(const int* __restrict__ src, const int* __restrict__ dst, int E) {
    int e = blockIdx.x * blockDim.x + threadIdx.x;
    if (e >= E) return;
    int slot = atomicAdd(&g_cursor[dst[e]], 1);
    g_csr_src[slot] = src[e];
}

// ---------------- bf16 tensor-core GEMM (m16n8k16), bf16 output ----------------
#define SPAD 136

__device__ __forceinline__ void mma_bf16(float c[4], uint32_t a0, uint32_t a1,
                                         uint32_t a2, uint32_t a3,
                                         uint32_t b0, uint32_t b1) {
    asm volatile(
        "mma.sync.aligned.m16n8k16.row.col.f32.bf16.bf16.f32 "
        "{%0,%1,%2,%3}, {%4,%5,%6,%7}, {%8,%9}, {%0,%1,%2,%3};"
        : "+f"(c[0]), "+f"(c[1]), "+f"(c[2]), "+f"(c[3])
        : "r"(a0), "r"(a1), "r"(a2), "r"(a3), "r"(b0), "r"(b1));
}

__global__ __launch_bounds__(256)
void gemm_bf16(const __nv_bfloat16* __restrict__ A, const uint32_t* __restrict__ Bp,
               __nv_bfloat16* __restrict__ Cb, int M, int K, int Ncol) {
    __shared__ uint32_t As[16][SPAD];   // [kpair][m]
    __shared__ uint32_t Bs[16][SPAD];   // [kpair][n]

    const int t = threadIdx.x;
    const int lane = t & 31;
    const int warp = t >> 5;
    const int wm = (warp & 1) * 64;
    const int wn = (warp >> 1) * 32;
    const int g = lane >> 2;
    const int t4 = lane & 3;

    const int rowBase = blockIdx.y * 128;
    const int colBase = blockIdx.x * 128;

    const int ar = t & 127;
    const int ah = t >> 7;
    const int bkp = t >> 4;
    const int bcol = (t & 15) * 8;

    float acc[4][4][4];
#pragma unroll
    for (int mt = 0; mt < 4; mt++)
#pragma unroll
        for (int nt = 0; nt < 4; nt++)
#pragma unroll
            for (int i = 0; i < 4; i++) acc[mt][nt][i] = 0.f;

    const int grow = rowBase + ar;
    const bool arow_ok = (grow < M);
    const __nv_bfloat16* aBase = A + (size_t)grow * K + ah * 16;
    const uint32_t* bBase = Bp + (size_t)bkp * Ncol + colBase + bcol;

    uint4 ra0, ra1, rb0, rb1;

    if (arow_ok) {
        ra0 = *(const uint4*)(aBase);
        ra1 = *(const uint4*)(aBase + 8);
    } else {
        ra0 = make_uint4(0, 0, 0, 0); ra1 = make_uint4(0, 0, 0, 0);
    }
    rb0 = *(const uint4*)(bBase);
    rb1 = *(const uint4*)(bBase + 4);

    const int nChunks = K >> 5;
    for (int ci = 0; ci < nChunks; ci++) {
        {
            const int kb = ah * 8;
            As[kb + 0][ar] = ra0.x; As[kb + 1][ar] = ra0.y;
            As[kb + 2][ar] = ra0.z; As[kb + 3][ar] = ra0.w;
            As[kb + 4][ar] = ra1.x; As[kb + 5][ar] = ra1.y;
            As[kb + 6][ar] = ra1.z; As[kb + 7][ar] = ra1.w;
            *(uint4*)&Bs[bkp][bcol]     = rb0;
            *(uint4*)&Bs[bkp][bcol + 4] = rb1;
        }
        __syncthreads();

        if (ci + 1 < nChunks) {
            int k0 = (ci + 1) << 5;
            if (arow_ok) {
                ra0 = *(const uint4*)(aBase + k0);
                ra1 = *(const uint4*)(aBase + k0 + 8);
            }
            rb0 = *(const uint4*)(bBase + (size_t)(k0 >> 1) * Ncol);
            rb1 = *(const uint4*)(bBase + (size_t)(k0 >> 1) * Ncol + 4);
        }

#pragma unroll
        for (int kk = 0; kk < 2; kk++) {
            const int kb = kk * 8;
            uint32_t af[4][4];
#pragma unroll
            for (int mt = 0; mt < 4; mt++) {
                int r = wm + mt * 16 + g;
                af[mt][0] = As[kb + t4][r];
                af[mt][1] = As[kb + t4][r + 8];
                af[mt][2] = As[kb + t4 + 4][r];
                af[mt][3] = As[kb + t4 + 4][r + 8];
            }
#pragma unroll
            for (int nt = 0; nt < 4; nt++) {
                int cn = wn + nt * 8 + g;
                uint32_t b0 = Bs[kb + t4][cn];
                uint32_t b1 = Bs[kb + t4 + 4][cn];
#pragma unroll
                for (int mt = 0; mt < 4; mt++)
                    mma_bf16(acc[mt][nt], af[mt][0], af[mt][1], af[mt][2], af[mt][3], b0, b1);
            }
        }
        __syncthreads();
    }

#pragma unroll
    for (int mt = 0; mt < 4; mt++) {
        int r0 = rowBase + wm + mt * 16 + g;
#pragma unroll
        for (int nt = 0; nt < 4; nt++) {
            int col = colBase + wn + nt * 8 + 2 * t4;
            if (r0 < M)
                *(__nv_bfloat162*)(Cb + (size_t)r0 * Ncol + col) =
                    __floats2bfloat162_rn(acc[mt][nt][0], acc[mt][nt][1]);
            if (r0 + 8 < M)
                *(__nv_bfloat162*)(Cb + (size_t)(r0 + 8) * Ncol + col) =
                    __floats2bfloat162_rn(acc[mt][nt][2], acc[mt][nt][3]);
        }
    }
}

// ---------------- bf16x4 -> 4 floats helper ----------------
__device__ __forceinline__ void bf4(uint2 u, float& f0, float& f1, float& f2, float& f3) {
    float2 p0 = __bfloat1622float2(*reinterpret_cast<__nv_bfloat162*>(&u.x));
    float2 p1 = __bfloat1622float2(*reinterpret_cast<__nv_bfloat162*>(&u.y));
    f0 = p0.x; f1 = p0.y; f2 = p1.x; f3 = p1.y;
}

// ---------------- fused pull-aggregation + node epilogue, layer 0 ----------------
__global__ __launch_bounds__(256)
void agg0_kernel(const float* __restrict__ bl0, const float* __restrict__ bp, int N) {
    int w = (blockIdx.x * blockDim.x + threadIdx.x) >> 5;
    int lane = threadIdx.x & 31;
    if (w >= N) return;
    int nbeg = g_rowptr[w], nend = g_rowptr[w + 1];
    float a0 = 0.f, a1 = 0.f, a2 = 0.f, a3 = 0.f;
    int j = nbeg;
    for (; j + 4 <= nend; j += 4) {
        int s0 = g_csr_src[j], s1 = g_csr_src[j + 1], s2 = g_csr_src[j + 2], s3 = g_csr_src[j + 3];
        uint2 v0 = *((const uint2*)(g_C1b + (size_t)s0 * 384) + lane);
        uint2 v1 = *((const uint2*)(g_C1b + (size_t)s1 * 384) + lane);
        uint2 v2 = *((const uint2*)(g_C1b + (size_t)s2 * 384) + lane);
        uint2 v3 = *((const uint2*)(g_C1b + (size_t)s3 * 384) + lane);
        float f0, f1, f2, f3;
        bf4(v0, f0, f1, f2, f3); a0 += f0; a1 += f1; a2 += f2; a3 += f3;
        bf4(v1, f0, f1, f2, f3); a0 += f0; a1 += f1; a2 += f2; a3 += f3;
        bf4(v2, f0, f1, f2, f3); a0 += f0; a1 += f1; a2 += f2; a3 += f3;
        bf4(v3, f0, f1, f2, f3); a0 += f0; a1 += f1; a2 += f2; a3 += f3;
    }
    for (; j < nend; j++) {
        int s = g_csr_src[j];
        uint2 v = *((const uint2*)(g_C1b + (size_t)s * 384) + lane);
        float f0, f1, f2, f3;
        bf4(v, f0, f1, f2, f3); a0 += f0; a1 += f1; a2 += f2; a3 += f3;
    }
    float dinv = 1.0f / fmaxf((float)(nend - nbeg), 1.0f);
    float r0, r1, r2, r3, p0, p1, p2, p3;
    bf4(*(const uint2*)(g_C1b + (size_t)w * 384 + 128 + lane * 4), r0, r1, r2, r3);
    bf4(*(const uint2*)(g_C1b + (size_t)w * 384 + 256 + lane * 4), p0, p1, p2, p3);
    float4 bl = *(const float4*)(bl0 + lane * 4);
    float4 bv = *(const float4*)(bp + lane * 4);
    float o0 = fmaxf(fmaf(a0, dinv, bl.x + r0), 0.f) + p0 + bv.x;
    float o1 = fmaxf(fmaf(a1, dinv, bl.y + r1), 0.f) + p1 + bv.y;
    float o2 = fmaxf(fmaf(a2, dinv, bl.z + r2), 0.f) + p2 + bv.z;
    float o3 = fmaxf(fmaf(a3, dinv, bl.w + r3), 0.f) + p3 + bv.w;
    __nv_bfloat162 q0 = __floats2bfloat162_rn(o0, o1);
    __nv_bfloat162 q1 = __floats2bfloat162_rn(o2, o3);
    uint2 qo; qo.x = *reinterpret_cast<uint32_t*>(&q0); qo.y = *reinterpret_cast<uint32_t*>(&q1);
    *((uint2*)(g_h1b + (size_t)w * DH) + lane) = qo;
}

// ---------------- fused pull-aggregation + node epilogue, layer 1 ----------------
__global__ __launch_bounds__(256)
void agg1_kernel(const float* __restrict__ bl1, int N) {
    int w = (blockIdx.x * blockDim.x + threadIdx.x) >> 5;
    int lane = threadIdx.x & 31;
    if (w >= N) return;
    int nbeg = g_rowptr[w], nend = g_rowptr[w + 1];
    float a0 = 0.f, a1 = 0.f, a2 = 0.f, a3 = 0.f;
    int j = nbeg;
    for (; j + 4 <= nend; j += 4) {
        int s0 = g_csr_src[j], s1 = g_csr_src[j + 1], s2 = g_csr_src[j + 2], s3 = g_csr_src[j + 3];
        uint2 v0 = *((const uint2*)(g_C2b + (size_t)s0 * 256) + lane);
        uint2 v1 = *((const uint2*)(g_C2b + (size_t)s1 * 256) + lane);
        uint2 v2 = *((const uint2*)(g_C2b + (size_t)s2 * 256) + lane);
        uint2 v3 = *((const uint2*)(g_C2b + (size_t)s3 * 256) + lane);
        float f0, f1, f2, f3;
        bf4(v0, f0, f1, f2, f3); a0 += f0; a1 += f1; a2 += f2; a3 += f3;
        bf4(v1, f0, f1, f2, f3); a0 += f0; a1 += f1; a2 += f2; a3 += f3;
        bf4(v2, f0, f1, f2, f3); a0 += f0; a1 += f1; a2 += f2; a3 += f3;
        bf4(v3, f0, f1, f2, f3); a0 += f0; a1 += f1; a2 += f2; a3 += f3;
    }
    for (; j < nend; j++) {
        int s = g_csr_src[j];
        uint2 v = *((const uint2*)(g_C2b + (size_t)s * 256) + lane);
        float f0, f1, f2, f3;
        bf4(v, f0, f1, f2, f3); a0 += f0; a1 += f1; a2 += f2; a3 += f3;
    }
    float dinv = 1.0f / fmaxf((float)(nend - nbeg), 1.0f);
    float r0, r1, r2, r3, h0, h1, h2, h3;
    bf4(*(const uint2*)(g_C2b + (size_t)w * 256 + 128 + lane * 4), r0, r1, r2, r3);
    bf4(*((const uint2*)(g_h1b + (size_t)w * DH) + lane), h0, h1, h2, h3);
    float4 bl = *(const float4*)(bl1 + lane * 4);
    float o0 = fmaxf(fmaf(a0, dinv, bl.x + r0), 0.f) + h0;
    float o1 = fmaxf(fmaf(a1, dinv, bl.y + r1), 0.f) + h1;
    float o2 = fmaxf(fmaf(a2, dinv, bl.z + r2), 0.f) + h2;
    float o3 = fmaxf(fmaf(a3, dinv, bl.w + r3), 0.f) + h3;
    __nv_bfloat162 q0 = __floats2bfloat162_rn(o0, o1);
    __nv_bfloat162 q1 = __floats2bfloat162_rn(o2, o3);
    uint2 qo; qo.x = *reinterpret_cast<uint32_t*>(&q0); qo.y = *reinterpret_cast<uint32_t*>(&q1);
    *((uint2*)(g_h2b + (size_t)w * DH) + lane) = qo;
}

// ---------------- MMA head: gnn = relu(h2b@W1 + b1)@W2 + b2; blend ----------------
__global__ __launch_bounds__(256)
void head_mma(const float* __restrict__ W1, const float* __restrict__ b1,
              const float* __restrict__ W2, const float* __restrict__ b2,
              const float* __restrict__ rer, const float* __restrict__ alogit,
              float* __restrict__ out, int N) {
    extern __shared__ uint32_t sm[];
    uint32_t* As = sm;               // 9216-word region (As uses 8704)
    uint32_t* Bs = sm + 9216;        // 4608 words
    float* Cs = (float*)sm;          // aliases As region after compute
    __shared__ float b1s[64];
    __shared__ float W2s[64];

    const int t = threadIdx.x;
    const int lane = t & 31;
    const int warp = t >> 5;
    const int wm = (warp & 1) * 64;
    const int wn = (warp >> 1) * 16;
    const int g = lane >> 2;
    const int t4 = lane & 3;
    const int rowBase = blockIdx.x * 128;

    for (int idx = t; idx < 64 * 64; idx += 256) {
        int kp = idx >> 6, col = idx & 63;
        __nv_bfloat162 p = __floats2bfloat162_rn(W1[(2 * kp) * 64 + col],
                                                 W1[(2 * kp + 1) * 64 + col]);
        Bs[kp * 72 + col] = *reinterpret_cast<uint32_t*>(&p);
    }
    if (t < 64) { b1s[t] = b1[t]; W2s[t] = W2[t]; }

    {
        int row = t & 127;
        int half = t >> 7;
        bool ok = (rowBase + row) < N;
        const uint4* aRow = (const uint4*)(g_h2b + (size_t)(rowBase + row) * DH);
#pragma unroll
        for (int q = 0; q < 8; q++) {
            uint4 u = ok ? aRow[half * 8 + q] : make_uint4(0, 0, 0, 0);
            int kp = (half * 8 + q) * 4;
            As[(kp + 0) * SPAD + row] = u.x;
            As[(kp + 1) * SPAD + row] = u.y;
            As[(kp + 2) * SPAD + row] = u.z;
            As[(kp + 3) * SPAD + row] = u.w;
        }
    }
    __syncthreads();

    float acc[4][2][4];
#pragma unroll
    for (int mt = 0; mt < 4; mt++)
#pragma unroll
        for (int nt = 0; nt < 2; nt++)
#pragma unroll
            for (int i = 0; i < 4; i++) acc[mt][nt][i] = 0.f;

#pragma unroll
    for (int step = 0; step < 8; step++) {
        const int kb = step * 8;
        uint32_t af[4][4];
#pragma unroll
        for (int mt = 0; mt < 4; mt++) {
            int r = wm + mt * 16 + g;
            af[mt][0] = As[(kb + t4) * SPAD + r];
            af[mt][1] = As[(kb + t4) * SPAD + r + 8];
            af[mt][2] = As[(kb + t4 + 4) * SPAD + r];
            af[mt][3] = As[(kb + t4 + 4) * SPAD + r + 8];
        }
#pragma unroll
        for (int nt = 0; nt < 2; nt++) {
            int cn = wn + nt * 8 + g;
            uint32_t b0 = Bs[(kb + t4) * 72 + cn];
            uint32_t b1r = Bs[(kb + t4 + 4) * 72 + cn];
#pragma unroll
            for (int mt = 0; mt < 4; mt++)
                mma_bf16(acc[mt][nt], af[mt][0], af[mt][1], af[mt][2], af[mt][3], b0, b1r);
        }
    }
    __syncthreads();

#pragma unroll
    for (int mt = 0; mt < 4; mt++) {
        int r = wm + mt * 16 + g;
#pragma unroll
        for (int nt = 0; nt < 2; nt++) {
            int col = wn + nt * 8 + 2 * t4;
            Cs[r * 72 + col]       = acc[mt][nt][0];
            Cs[r * 72 + col + 1]   = acc[mt][nt][1];
            Cs[(r + 8) * 72 + col]     = acc[mt][nt][2];
            Cs[(r + 8) * 72 + col + 1] = acc[mt][nt][3];
        }
    }
    __syncthreads();

    {
        int row = t >> 1;
        int hc = (t & 1) * 32;
        float s = 0.f;
#pragma unroll
        for (int c = 0; c < 32; c++) {
            int col = hc + c;
            s = fmaf(fmaxf(Cs[row * 72 + col] + b1s[col], 0.f), W2s[col], s);
        }
        s += __shfl_xor_sync(0xffffffffu, s, 1);
        int gr = rowBase + row;
        if ((t & 1) == 0 && gr < N) {
            float gnn = s + b2[0];
            float alpha = 1.0f / (1.0f + __expf(-alogit[0]));
            out[gr] = alpha * rer[gr] + (1.0f - alpha) * gnn;
        }
    }
}

// ---------------- launch ----------------
extern "C" void kernel_launch(void* const* d_in, const int* in_sizes, int n_in,
                              void* d_out, int out_size) {
    const float* x     = (const float*)d_in[0];
    const int*   eidx  = (const int*)d_in[1];
    const float* rer   = (const float*)d_in[2];
    const float* Wp    = (const float*)d_in[3];
    const float* bp    = (const float*)d_in[4];
    const float* Wl0   = (const float*)d_in[5];
    const float* bl0   = (const float*)d_in[6];
    const float* Wr0   = (const float*)d_in[7];
    const float* Wl1   = (const float*)d_in[8];
    const float* bl1   = (const float*)d_in[9];
    const float* Wr1   = (const float*)d_in[10];
    const float* W1    = (const float*)d_in[11];
    const float* b1    = (const float*)d_in[12];
    const float* W2    = (const float*)d_in[13];
    const float* b2    = (const float*)d_in[14];
    const float* alog  = (const float*)d_in[15];
    float* out = (float*)d_out;

    const int N = in_sizes[0] / DIN;       // 50000
    const int E = in_sizes[1] / 2;         // 800000
    const int* src = eidx;
    const int* dst = eidx + E;

    __nv_bfloat16 *C1b, *C2b, *xb, *h1b;
    uint32_t *Bp1b, *Bp2b;
    cudaGetSymbolAddress((void**)&C1b,  g_C1b);
    cudaGetSymbolAddress((void**)&C2b,  g_C2b);
    cudaGetSymbolAddress((void**)&xb,   g_xb);
    cudaGetSymbolAddress((void**)&h1b,  g_h1b);
    cudaGetSymbolAddress((void**)&Bp1b, g_Bp1b);
    cudaGetSymbolAddress((void**)&Bp2b, g_Bp2b);

    static int init_done = 0;
    if (!init_done) {
        cudaFuncSetAttribute(head_mma, cudaFuncAttributeMaxDynamicSharedMemorySize, 55296);
        if (!g_s2) {   // fallback if static initializer ran before CUDA was ready
            cudaStreamCreateWithFlags(&g_s2, cudaStreamNonBlocking);
            cudaEventCreateWithFlags(&g_evFork, cudaEventDisableTiming);
            cudaEventCreateWithFlags(&g_evJoin, cudaEventDisableTiming);
        }
        init_done = 1;
    }

    // ---- fork side stream for CSR build ----
    cudaEventRecord(g_evFork, 0);
    cudaStreamWaitEvent(g_s2, g_evFork, 0);

    zero_deg<<<(N + 255) / 256, 256, 0, g_s2>>>(N);
    hist_kernel<<<(E + 255) / 256, 256, 0, g_s2>>>(dst, E);
    int nb = (N + 1023) / 1024;
    scan_blocks<<<nb, 1024, 0, g_s2>>>(N);
    scan_add_fused<<<(N + 255) / 256, 256, 0, g_s2>>>(N);
    csr_fill<<<(E + 255) / 256, 256, 0, g_s2>>>(src, dst, E);
    cudaEventRecord(g_evJoin, g_s2);

    // ---- main stream: pack, convert, GEMM1 (concurrent with CSR build) ----
    pack_kernel<<<((DIN / 2) * 384 + 255) / 256, 256>>>(Wl0, Wr0, Wp, Wl1, Wr1);
    {
        int nWords = N * DIN / 2;
        convert_x<<<(nWords + 255) / 256, 256>>>(x, nWords);
    }
    {
        dim3 grid(384 / 128, (N + 127) / 128);
        gemm_bf16<<<grid, 256>>>(xb, Bp1b, C1b, N, DIN, 384);
    }

    // ---- join: agg0 needs CSR + GEMM1 ----
    cudaStreamWaitEvent(0, g_evJoin, 0);
    agg0_kernel<<<(N * 32 + 255) / 256, 256>>>(bl0, bp, N);

    // GEMM2: h1b[N,128] @ Bp2b -> C2b bf16 [N,256] (msg | r1)
    {
        dim3 grid(256 / 128, (N + 127) / 128);
        gemm_bf16<<<grid, 256>>>(h1b, Bp2b, C2b, N, DH, 256);
    }

    // pull-agg layer 1 + epilogue -> h2 bf16
    agg1_kernel<<<(N * 32 + 255) / 256, 256>>>(bl1, N);

    // MMA head + blend
    head_mma<<<(N + 127) / 128, 256, 55296>>>(W1, b1, W2, b2, rer, alog, out, N);
}